// round 2
// baseline (speedup 1.0000x reference)
#include <cuda_runtime.h>
#include <math.h>
#include <stdint.h>

// HAN: S=256 sentences x W=64 words, E=256, HW=HS=256, C=10
// Inputs (metadata order):
//  0 tokens[S*W] int32, 1 emb[100000*256] f32,
//  2 wWihF[768,256] 3 wWhhF[768,256] 4 wBihF[768] 5 wBhhF[768]
//  6 wWihB[768,256] 7 wWhhB[768,256] 8 wBihB[768] 9 wBhhB[768]
// 10 sWihF[768,512] 11 sWhhF[768,256] 12 sBihF[768] 13 sBhhF[768]
// 14 sWihB[768,512] 15 sWhhB[768,256] 16 sBihB[768] 17 sBhhB[768]
// 18 wAttW[512] 19 wAttB[1] 20 sAttW[512] 21 sAttB[1]
// 22 clsW[10,512] 23 clsB[10]  -> out float[10]

#define SN 256
#define WN 64
#define EN 256
#define HWD 256
#define G3 768

// ---------------- static device scratch ----------------
__device__ float g_xg[2][WN][SN][G3];      // word input gates, time-major
__device__ float g_wordout[SN][WN][512];   // word BiGRU outputs (F 0..255, B 256..511)
__device__ float g_sent[SN][512];          // sentence vectors
__device__ float g_sxg[2][SN][G3];         // sentence input gates
__device__ float g_sentout[SN][512];       // sentence BiGRU outputs
__device__ float g_hbuf[2][2][SN][HWD];    // word rec h exchange [parity][dir][s][u]
__device__ float g_shbuf[2][2][HWD];       // sent rec h exchange [parity][dir][u]
__device__ unsigned g_bars[32];            // barrier counters

__device__ __forceinline__ float sigf(float x) { return 1.0f / (1.0f + expf(-x)); }

__global__ void k_zero_bars() {
    if (threadIdx.x < 32) g_bars[threadIdx.x] = 0u;
}

// ---------------- kernel 1: word input gates (gathered SGEMM) ----------------
// grid (24, 256): 24 col tiles of 64 (F cols 0..767, B cols 768..1535), one sentence per blockIdx.y
__global__ void __launch_bounds__(256) k_word_gates(
    const int* __restrict__ toks, const float* __restrict__ emb,
    const float* __restrict__ WihF, const float* __restrict__ WihB,
    const float* __restrict__ bihF, const float* __restrict__ bihB)
{
    __shared__ float As[32][68];
    __shared__ float Bs[32][68];
    __shared__ int stok[64];
    const int s   = blockIdx.y;
    const int c0  = blockIdx.x * 64;
    const int dir = (c0 >= G3) ? 1 : 0;
    const int gc0 = c0 - dir * G3;
    const float* __restrict__ Wih = dir ? WihB : WihF;
    const float* __restrict__ bih = dir ? bihB : bihF;
    const int tid = threadIdx.x;
    if (tid < 64) stok[tid] = toks[s * WN + tid];
    __syncthreads();
    const int tx = tid & 15, ty = tid >> 4;
    const int lr = tid >> 3, lk = (tid & 7) << 2;
    float acc[4][4];
#pragma unroll
    for (int i = 0; i < 4; i++)
#pragma unroll
        for (int j = 0; j < 4; j++) acc[i][j] = 0.0f;

    for (int k0 = 0; k0 < EN; k0 += 32) {
#pragma unroll
        for (int p = 0; p < 2; p++) {
            const int r = p * 32 + lr;
            float4 av = *(const float4*)&emb[(size_t)stok[r] * EN + k0 + lk];
            As[lk + 0][r] = av.x; As[lk + 1][r] = av.y;
            As[lk + 2][r] = av.z; As[lk + 3][r] = av.w;
            float4 bv = *(const float4*)&Wih[(size_t)(gc0 + r) * EN + k0 + lk];
            Bs[lk + 0][r] = bv.x; Bs[lk + 1][r] = bv.y;
            Bs[lk + 2][r] = bv.z; Bs[lk + 3][r] = bv.w;
        }
        __syncthreads();
#pragma unroll
        for (int k = 0; k < 32; k++) {
            float4 a = *(const float4*)&As[k][ty * 4];
            float4 b = *(const float4*)&Bs[k][tx * 4];
            float av4[4] = {a.x, a.y, a.z, a.w};
            float bv4[4] = {b.x, b.y, b.z, b.w};
#pragma unroll
            for (int i = 0; i < 4; i++)
#pragma unroll
                for (int j = 0; j < 4; j++) acc[i][j] += av4[i] * bv4[j];
        }
        __syncthreads();
    }
    const int gcw = gc0 + tx * 4;
    const float b0 = bih[gcw + 0], b1 = bih[gcw + 1], b2 = bih[gcw + 2], b3 = bih[gcw + 3];
#pragma unroll
    for (int i = 0; i < 4; i++) {
        const int w = ty * 4 + i;
        float4 o;
        o.x = acc[i][0] + b0; o.y = acc[i][1] + b1;
        o.z = acc[i][2] + b2; o.w = acc[i][3] + b3;
        *(float4*)&g_xg[dir][w][s][gcw] = o;
    }
}

// ---------------- kernel 2: word recurrence (persistent, global barrier) ----------------
// grid 128 = dir(2) x sent-tile(8 x 32 sents) x unit-tile(8 x 32 units), 256 threads
__global__ void __launch_bounds__(256) k_word_rec(
    const float* __restrict__ WhhF, const float* __restrict__ WhhB,
    const float* __restrict__ bhhF, const float* __restrict__ bhhB)
{
    extern __shared__ float sm[];
    float* ws  = sm;                 // [3*256][32]  (gate-k major, unit minor)
    float* hs  = ws + 3 * 256 * 32;  // [32][256]
    float* sbh = hs + 32 * 256;      // [96]
    const int blk = blockIdx.x;
    const int dir = blk >> 6;
    const int st  = (blk >> 3) & 7;
    const int ut  = blk & 7;
    const int u0  = ut * 32;
    const int grp = dir * 8 + st;
    const float* __restrict__ Whh = dir ? WhhB : WhhF;
    const float* __restrict__ bhh = dir ? bhhB : bhhF;
    const int tid = threadIdx.x;
    const int u = tid & 31, sg = tid >> 5;

    // load Whh slice transposed into smem: ws[(g*256+k)*32 + uu]
    for (int r = tid >> 3; r < 96; r += 32) {
        const int g = r >> 5, uu = r & 31;
        const float* wrow = &Whh[(size_t)(g * 256 + u0 + uu) * 256];
        for (int kk = (tid & 7) << 2; kk < 256; kk += 32) {
            float4 v = *(const float4*)&wrow[kk];
            ws[(g * 256 + kk + 0) * 32 + uu] = v.x;
            ws[(g * 256 + kk + 1) * 32 + uu] = v.y;
            ws[(g * 256 + kk + 2) * 32 + uu] = v.z;
            ws[(g * 256 + kk + 3) * 32 + uu] = v.w;
        }
    }
    if (tid < 96) sbh[tid] = bhh[(tid >> 5) * 256 + u0 + (tid & 31)];
    for (int i = tid; i < 32 * 256; i += 256) hs[i] = 0.0f;
    __syncthreads();

    const float* wsu = ws + u;
    const float bh_r = sbh[u], bh_z = sbh[32 + u], bh_n = sbh[64 + u];
    const int uc = u0 + u;

    for (int t = 0; t < 64; t++) {
        const int tt = dir ? (63 - t) : t;
        // prefetch x-gates (hide DRAM latency behind the k-loop)
        float xr[4], xz[4], xn[4];
#pragma unroll
        for (int j = 0; j < 4; j++) {
            const int s = st * 32 + sg * 4 + j;
            xr[j] = g_xg[dir][tt][s][uc];
            xz[j] = g_xg[dir][tt][s][256 + uc];
            xn[j] = g_xg[dir][tt][s][512 + uc];
        }
        float acc[3][4];
#pragma unroll
        for (int g = 0; g < 3; g++)
#pragma unroll
            for (int j = 0; j < 4; j++) acc[g][j] = 0.0f;

        for (int k = 0; k < 256; k += 4) {
            float ha[4][4];
#pragma unroll
            for (int j = 0; j < 4; j++)
                *(float4*)ha[j] = *(const float4*)&hs[(sg * 4 + j) * 256 + k];
#pragma unroll
            for (int kk = 0; kk < 4; kk++) {
                const float w0 = wsu[(k + kk) * 32];
                const float w1 = wsu[(256 + k + kk) * 32];
                const float w2 = wsu[(512 + k + kk) * 32];
#pragma unroll
                for (int j = 0; j < 4; j++) {
                    acc[0][j] += w0 * ha[j][kk];
                    acc[1][j] += w1 * ha[j][kk];
                    acc[2][j] += w2 * ha[j][kk];
                }
            }
        }
        const int par = (t + 1) & 1;
#pragma unroll
        for (int j = 0; j < 4; j++) {
            const int sl = sg * 4 + j;
            const int s  = st * 32 + sl;
            const float r = sigf(xr[j] + acc[0][j] + bh_r);
            const float z = sigf(xz[j] + acc[1][j] + bh_z);
            const float n = tanhf(xn[j] + r * (acc[2][j] + bh_n));
            const float hold = hs[sl * 256 + uc];
            const float hnew = (1.0f - z) * n + z * hold;
            __stcg(&g_hbuf[par][dir][s][uc], hnew);
            g_wordout[s][tt][dir * 256 + uc] = hnew;
        }
        __threadfence();
        __syncthreads();
        if (tid == 0) {
            atomicAdd(&g_bars[grp], 1u);
            const unsigned tgt = 8u * (unsigned)(t + 1);
            while (*(volatile unsigned*)&g_bars[grp] < tgt) { }
        }
        __syncthreads();
        __threadfence();
        if (t < 63) {
            const float* src = &g_hbuf[par][dir][st * 32][0];
            for (int i = tid * 4; i < 32 * 256; i += 256 * 4)
                *(float4*)&hs[i] = __ldcg((const float4*)(src + i));
            __syncthreads();
        }
    }
}

// ---------------- kernel 3: word attention pool -> sentence vectors ----------------
__global__ void __launch_bounds__(256) k_word_attn(
    const float* __restrict__ attw, const float* __restrict__ attb)
{
    __shared__ float sc[64];
    const int s = blockIdx.x;
    const int tid = threadIdx.x, wp = tid >> 5, ln = tid & 31;
    const float bb = attb[0];
    for (int w = wp; w < 64; w += 8) {
        const float* op = &g_wordout[s][w][0];
        float d = 0.0f;
#pragma unroll
        for (int i = 0; i < 4; i++) {
            float4 o = *(const float4*)&op[ln * 16 + i * 4];
            float4 a = *(const float4*)&attw[ln * 16 + i * 4];
            d += o.x * a.x + o.y * a.y + o.z * a.z + o.w * a.w;
        }
#pragma unroll
        for (int off = 16; off > 0; off >>= 1) d += __shfl_xor_sync(0xffffffffu, d, off);
        if (ln == 0) sc[w] = tanhf(d + bb);
    }
    __syncthreads();
    if (tid < 32) {
        float a0 = sc[tid], a1 = sc[tid + 32];
        float m = fmaxf(a0, a1);
#pragma unroll
        for (int off = 16; off > 0; off >>= 1) m = fmaxf(m, __shfl_xor_sync(0xffffffffu, m, off));
        float e0 = expf(a0 - m), e1 = expf(a1 - m);
        float ssum = e0 + e1;
#pragma unroll
        for (int off = 16; off > 0; off >>= 1) ssum += __shfl_xor_sync(0xffffffffu, ssum, off);
        sc[tid] = e0 / ssum; sc[tid + 32] = e1 / ssum;
    }
    __syncthreads();
    float acc0 = 0.0f, acc1 = 0.0f;
    for (int w = 0; w < 64; w++) {
        const float a = sc[w];
        acc0 += a * g_wordout[s][w][tid];
        acc1 += a * g_wordout[s][w][tid + 256];
    }
    g_sent[s][tid] = acc0;
    g_sent[s][tid + 256] = acc1;
}

// ---------------- kernel 4: sentence input gates (SGEMM, K=512) ----------------
// grid (24, 4): 64-col tiles x 64-sentence tiles
__global__ void __launch_bounds__(256) k_sent_gates(
    const float* __restrict__ WihF, const float* __restrict__ WihB,
    const float* __restrict__ bihF, const float* __restrict__ bihB)
{
    __shared__ float As[32][68];
    __shared__ float Bs[32][68];
    const int s0  = blockIdx.y * 64;
    const int c0  = blockIdx.x * 64;
    const int dir = (c0 >= G3) ? 1 : 0;
    const int gc0 = c0 - dir * G3;
    const float* __restrict__ Wih = dir ? WihB : WihF;
    const float* __restrict__ bih = dir ? bihB : bihF;
    const int tid = threadIdx.x;
    const int tx = tid & 15, ty = tid >> 4;
    const int lr = tid >> 3, lk = (tid & 7) << 2;
    float acc[4][4];
#pragma unroll
    for (int i = 0; i < 4; i++)
#pragma unroll
        for (int j = 0; j < 4; j++) acc[i][j] = 0.0f;

    for (int k0 = 0; k0 < 512; k0 += 32) {
#pragma unroll
        for (int p = 0; p < 2; p++) {
            const int r = p * 32 + lr;
            float4 av = *(const float4*)&g_sent[s0 + r][k0 + lk];
            As[lk + 0][r] = av.x; As[lk + 1][r] = av.y;
            As[lk + 2][r] = av.z; As[lk + 3][r] = av.w;
            float4 bv = *(const float4*)&Wih[(size_t)(gc0 + r) * 512 + k0 + lk];
            Bs[lk + 0][r] = bv.x; Bs[lk + 1][r] = bv.y;
            Bs[lk + 2][r] = bv.z; Bs[lk + 3][r] = bv.w;
        }
        __syncthreads();
#pragma unroll
        for (int k = 0; k < 32; k++) {
            float4 a = *(const float4*)&As[k][ty * 4];
            float4 b = *(const float4*)&Bs[k][tx * 4];
            float av4[4] = {a.x, a.y, a.z, a.w};
            float bv4[4] = {b.x, b.y, b.z, b.w};
#pragma unroll
            for (int i = 0; i < 4; i++)
#pragma unroll
                for (int j = 0; j < 4; j++) acc[i][j] += av4[i] * bv4[j];
        }
        __syncthreads();
    }
    const int gcw = gc0 + tx * 4;
    const float b0 = bih[gcw + 0], b1 = bih[gcw + 1], b2 = bih[gcw + 2], b3 = bih[gcw + 3];
#pragma unroll
    for (int i = 0; i < 4; i++) {
        float4 o;
        o.x = acc[i][0] + b0; o.y = acc[i][1] + b1;
        o.z = acc[i][2] + b2; o.w = acc[i][3] + b3;
        *(float4*)&g_sxg[dir][s0 + ty * 4 + i][gcw] = o;
    }
}

// ---------------- kernel 5: sentence recurrence (persistent, 8 blocks/dir) ----------------
// grid 16 = dir(2) x unit-tile(8 x 32 units), 192 threads (2 threads per gate-row, k halves)
__global__ void __launch_bounds__(192) k_sent_rec(
    const float* __restrict__ WhhF, const float* __restrict__ WhhB,
    const float* __restrict__ bhhF, const float* __restrict__ bhhB)
{
    extern __shared__ float sm2[];
    float* wsm = sm2;                 // 192 half-rows x 132 (padded)
    float* hsh = wsm + 192 * 132;     // [256]
    float* gv  = hsh + 256;           // [96]
    const int dir = blockIdx.x >> 3;
    const int ut  = blockIdx.x & 7;
    const int u0  = ut * 32;
    const int grp = 16 + dir;
    const float* __restrict__ Whh = dir ? WhhB : WhhF;
    const float* __restrict__ bhh = dir ? bhhB : bhhF;
    const int tid = threadIdx.x;

    // init weights: row r (0..95) maps to gate g=r/32, unit u0+r%32
    for (int idx = tid; idx < 96 * 256; idx += 192) {
        const int r = idx >> 8, k = idx & 255;
        const int row_g = (r >> 5) * 256 + u0 + (r & 31);
        wsm[(r * 2 + (k >> 7)) * 132 + (k & 127)] = Whh[(size_t)row_g * 256 + k];
    }
    for (int k = tid; k < 256; k += 192) hsh[k] = 0.0f;
    __syncthreads();

    const int r = tid >> 1, half = tid & 1;
    const int row_g = (r >> 5) * 256 + u0 + (r & 31);
    const float bh = bhh[row_g];
    const float* wp = &wsm[tid * 132];
    const int hbase = half * 128;

    for (int t = 0; t < 256; t++) {
        const int tt = dir ? (255 - t) : t;
        // prefetch x-gates for combiner threads
        float xr = 0.0f, xz = 0.0f, xn = 0.0f, hold = 0.0f;
        if (tid < 32) {
            const int u = u0 + tid;
            xr = g_sxg[dir][tt][u];
            xz = g_sxg[dir][tt][256 + u];
            xn = g_sxg[dir][tt][512 + u];
            hold = hsh[u];
        }
        float acc = 0.0f;
#pragma unroll
        for (int i = 0; i < 32; i++) {
            float4 h4 = *(const float4*)&hsh[hbase + i * 4];
            float4 w4 = *(const float4*)&wp[i * 4];
            acc += h4.x * w4.x + h4.y * w4.y + h4.z * w4.z + h4.w * w4.w;
        }
        acc += __shfl_xor_sync(0xffffffffu, acc, 1);
        if (half == 0) gv[r] = acc + bh;
        __syncthreads();
        const int par = (t + 1) & 1;
        if (tid < 32) {
            const int u = u0 + tid;
            const float rr = sigf(xr + gv[tid]);
            const float zz = sigf(xz + gv[32 + tid]);
            const float nn = tanhf(xn + rr * gv[64 + tid]);
            const float hnew = (1.0f - zz) * nn + zz * hold;
            __stcg(&g_shbuf[par][dir][u], hnew);
            g_sentout[tt][dir * 256 + u] = hnew;
        }
        __threadfence();
        __syncthreads();
        if (tid == 0) {
            atomicAdd(&g_bars[grp], 1u);
            const unsigned tgt = 8u * (unsigned)(t + 1);
            while (*(volatile unsigned*)&g_bars[grp] < tgt) { }
        }
        __syncthreads();
        __threadfence();
        if (t < 255) {
            for (int k = tid; k < 256; k += 192) hsh[k] = __ldcg(&g_shbuf[par][dir][k]);
            __syncthreads();
        }
    }
}

// ---------------- kernel 6: sentence attention + classifier + softmax ----------------
__global__ void __launch_bounds__(256) k_doc(
    const float* __restrict__ attw, const float* __restrict__ attb,
    const float* __restrict__ clsW, const float* __restrict__ clsB,
    float* __restrict__ out)
{
    __shared__ float sc[256];
    __shared__ float red[8];
    __shared__ float docv[512];
    __shared__ float lg[10];
    const int tid = threadIdx.x, wp = tid >> 5, ln = tid & 31;
    const float bb = attb[0];
    for (int s = wp; s < 256; s += 8) {
        const float* op = &g_sentout[s][0];
        float d = 0.0f;
#pragma unroll
        for (int i = 0; i < 4; i++) {
            float4 o = *(const float4*)&op[ln * 16 + i * 4];
            float4 a = *(const float4*)&attw[ln * 16 + i * 4];
            d += o.x * a.x + o.y * a.y + o.z * a.z + o.w * a.w;
        }
#pragma unroll
        for (int off = 16; off > 0; off >>= 1) d += __shfl_xor_sync(0xffffffffu, d, off);
        if (ln == 0) sc[s] = tanhf(d + bb);
    }
    __syncthreads();
    // softmax over 256 scores
    float v = sc[tid];
    float m = v;
#pragma unroll
    for (int off = 16; off > 0; off >>= 1) m = fmaxf(m, __shfl_xor_sync(0xffffffffu, m, off));
    if (ln == 0) red[wp] = m;
    __syncthreads();
    if (tid < 8) {
        float mm = red[tid];
#pragma unroll
        for (int off = 4; off > 0; off >>= 1) mm = fmaxf(mm, __shfl_xor_sync(0xffu, mm, off));
        red[tid] = mm;
    }
    __syncthreads();
    const float gm = red[0];
    float e = expf(v - gm);
    float ssum = e;
#pragma unroll
    for (int off = 16; off > 0; off >>= 1) ssum += __shfl_xor_sync(0xffffffffu, ssum, off);
    __syncthreads();
    if (ln == 0) red[wp] = ssum;
    __syncthreads();
    if (tid < 8) {
        float s2 = red[tid];
#pragma unroll
        for (int off = 4; off > 0; off >>= 1) s2 += __shfl_xor_sync(0xffu, s2, off);
        red[tid] = s2;
    }
    __syncthreads();
    const float tot = red[0];
    sc[tid] = e / tot;
    __syncthreads();
    // weighted sum -> doc vector
    float a0 = 0.0f, a1 = 0.0f;
    for (int s = 0; s < 256; s++) {
        const float a = sc[s];
        a0 += a * g_sentout[s][tid];
        a1 += a * g_sentout[s][tid + 256];
    }
    docv[tid] = a0; docv[tid + 256] = a1;
    __syncthreads();
    // classifier: 10 x dot(512)
    for (int o = wp; o < 10; o += 8) {
        const float* wr = &clsW[o * 512];
        float d = 0.0f;
#pragma unroll
        for (int i = 0; i < 4; i++) {
            float4 x = *(const float4*)&docv[ln * 16 + i * 4];
            float4 w = *(const float4*)&wr[ln * 16 + i * 4];
            d += x.x * w.x + x.y * w.y + x.z * w.z + x.w * w.w;
        }
#pragma unroll
        for (int off = 16; off > 0; off >>= 1) d += __shfl_xor_sync(0xffffffffu, d, off);
        if (ln == 0) lg[o] = d + clsB[o];
    }
    __syncthreads();
    if (tid == 0) {
        float mm = lg[0];
        for (int i = 1; i < 10; i++) mm = fmaxf(mm, lg[i]);
        float s2 = 0.0f;
        float ee[10];
        for (int i = 0; i < 10; i++) { ee[i] = expf(lg[i] - mm); s2 += ee[i]; }
        for (int i = 0; i < 10; i++) out[i] = ee[i] / s2;
    }
}

// ---------------- launch ----------------
extern "C" void kernel_launch(void* const* d_in, const int* in_sizes, int n_in,
                              void* d_out, int out_size) {
    const int*   toks  = (const int*)d_in[0];
    const float* emb   = (const float*)d_in[1];
    const float* wWihF = (const float*)d_in[2];
    const float* wWhhF = (const float*)d_in[3];
    const float* wBihF = (const float*)d_in[4];
    const float* wBhhF = (const float*)d_in[5];
    const float* wWihB = (const float*)d_in[6];
    const float* wWhhB = (const float*)d_in[7];
    const float* wBihB = (const float*)d_in[8];
    const float* wBhhB = (const float*)d_in[9];
    const float* sWihF = (const float*)d_in[10];
    const float* sWhhF = (const float*)d_in[11];
    const float* sBihF = (const float*)d_in[12];
    const float* sBhhF = (const float*)d_in[13];
    const float* sWihB = (const float*)d_in[14];
    const float* sWhhB = (const float*)d_in[15];
    const float* sBihB = (const float*)d_in[16];
    const float* sBhhB = (const float*)d_in[17];
    const float* wAttW = (const float*)d_in[18];
    const float* wAttB = (const float*)d_in[19];
    const float* sAttW = (const float*)d_in[20];
    const float* sAttB = (const float*)d_in[21];
    const float* clsW  = (const float*)d_in[22];
    const float* clsB  = (const float*)d_in[23];
    float* out = (float*)d_out;

    const int WREC_SMEM = (3 * 256 * 32 + 32 * 256 + 96) * 4;       // 131456
    const int SREC_SMEM = (192 * 132 + 256 + 96) * 4;               // 102784
    cudaFuncSetAttribute(k_word_rec, cudaFuncAttributeMaxDynamicSharedMemorySize, WREC_SMEM);
    cudaFuncSetAttribute(k_sent_rec, cudaFuncAttributeMaxDynamicSharedMemorySize, SREC_SMEM);

    k_zero_bars<<<1, 32>>>();
    dim3 g1(24, 256);
    k_word_gates<<<g1, 256>>>(toks, emb, wWihF, wWihB, wBihF, wBihB);
    k_word_rec<<<128, 256, WREC_SMEM>>>(wWhhF, wWhhB, wBhhF, wBhhB);
    k_word_attn<<<256, 256>>>(wAttW, wAttB);
    dim3 g2(24, 4);
    k_sent_gates<<<g2, 256>>>(sWihF, sWihB, sBihF, sBihB);
    k_sent_rec<<<16, 192, SREC_SMEM>>>(sWhhF, sWhhB, sBhhF, sBhhB);
    k_doc<<<1, 256>>>(sAttW, sAttB, clsW, clsB, out);
}

// round 6
// speedup vs baseline: 1.1843x; 1.1843x over previous
#include <cuda_runtime.h>
#include <math.h>
#include <stdint.h>

// HAN: S=256 sentences x W=64 words, E=256, HW=HS=256, C=10
#define SN 256
#define WN 64
#define EN 256
#define HWD 256
#define G3 768

typedef unsigned long long ull;

// ---------------- static device scratch ----------------
__device__ float g_xg[2][WN][SN][G3];      // word input gates, time-major
__device__ float g_wordout[SN][WN][512];   // word BiGRU outputs (F 0..255, B 256..511)
__device__ float g_sent[SN][512];          // sentence vectors
__device__ float g_sxg[2][SN][G3];         // sentence input gates
__device__ float g_sentout[SN][512];       // sentence BiGRU outputs
__device__ float g_hbuf[2][2][SN][HWD];    // word rec h exchange [parity][dir][s][u]
__device__ float g_shbuf[2][2][HWD];       // sent rec h exchange [parity][dir][u]
__device__ unsigned g_bars[32];            // barrier counters

// ---------------- helpers ----------------
__device__ __forceinline__ void fma2(ull& d, ull a, ull b) {
    asm("fma.rn.f32x2 %0, %1, %2, %0;" : "+l"(d) : "l"(a), "l"(b));
}
__device__ __forceinline__ float2 asf2(ull v) {
    float2 r; asm("mov.b64 {%0, %1}, %2;" : "=f"(r.x), "=f"(r.y) : "l"(v)); return r;
}
__device__ __forceinline__ float sigf(float x) {
    return __fdividef(1.0f, 1.0f + __expf(-x));
}
__device__ __forceinline__ float tanh_fast(float x) {
    float e = __expf(-2.0f * x);
    return (1.0f - e) * __fdividef(1.0f, 1.0f + e);
}
__device__ __forceinline__ void bar_arrive(unsigned* p) {
    asm volatile("red.release.gpu.add.u32 [%0], %1;" :: "l"(p), "r"(1u) : "memory");
}
__device__ __forceinline__ unsigned bar_poll(const unsigned* p) {
    unsigned v;
    asm volatile("ld.acquire.gpu.u32 %0, [%1];" : "=r"(v) : "l"(p) : "memory");
    return v;
}

__global__ void k_zero_bars() {
    if (threadIdx.x < 32) g_bars[threadIdx.x] = 0u;
}

// ---------------- kernel 1: word input gates (gathered SGEMM, f32x2) ----------------
// grid (24, 256): 24 col tiles of 64 (F 0..767, B 768..1535), one sentence per blockIdx.y
__global__ void __launch_bounds__(256) k_word_gates(
    const int* __restrict__ toks, const float* __restrict__ emb,
    const float* __restrict__ WihF, const float* __restrict__ WihB,
    const float* __restrict__ bihF, const float* __restrict__ bihB)
{
    __shared__ float As[64][36];   // [row][k0..31 + pad]
    __shared__ float Bs[64][36];
    __shared__ int stok[64];
    const int s   = blockIdx.y;
    const int c0  = blockIdx.x * 64;
    const int dir = (c0 >= G3) ? 1 : 0;
    const int gc0 = c0 - dir * G3;
    const float* __restrict__ Wih = dir ? WihB : WihF;
    const float* __restrict__ bih = dir ? bihB : bihF;
    const int tid = threadIdx.x;
    if (tid < 64) stok[tid] = toks[s * WN + tid];
    __syncthreads();
    const int tx = tid & 15, ty = tid >> 4;
    const int lr = tid >> 3, lk = (tid & 7) << 2;
    ull acc2[4][4];
#pragma unroll
    for (int i = 0; i < 4; i++)
#pragma unroll
        for (int j = 0; j < 4; j++) acc2[i][j] = 0ull;

    for (int k0 = 0; k0 < EN; k0 += 32) {
#pragma unroll
        for (int p = 0; p < 2; p++) {
            const int r = p * 32 + lr;
            *(float4*)&As[r][lk] = *(const float4*)&emb[(size_t)stok[r] * EN + k0 + lk];
            *(float4*)&Bs[r][lk] = *(const float4*)&Wih[(size_t)(gc0 + r) * EN + k0 + lk];
        }
        __syncthreads();
#pragma unroll
        for (int k = 0; k < 32; k += 4) {
            ulonglong2 a_[4], b_[4];
#pragma unroll
            for (int i = 0; i < 4; i++) a_[i] = *(const ulonglong2*)&As[ty * 4 + i][k];
#pragma unroll
            for (int j = 0; j < 4; j++) b_[j] = *(const ulonglong2*)&Bs[tx + 16 * j][k];
#pragma unroll
            for (int i = 0; i < 4; i++)
#pragma unroll
                for (int j = 0; j < 4; j++) {
                    fma2(acc2[i][j], a_[i].x, b_[j].x);
                    fma2(acc2[i][j], a_[i].y, b_[j].y);
                }
        }
        __syncthreads();
    }
#pragma unroll
    for (int j = 0; j < 4; j++) {
        const int cgl = gc0 + tx + 16 * j;
        const float bj = bih[cgl];
#pragma unroll
        for (int i = 0; i < 4; i++) {
            float2 f = asf2(acc2[i][j]);
            g_xg[dir][ty * 4 + i][s][cgl] = f.x + f.y + bj;
        }
    }
}

// ---------------- kernel 2: word recurrence (persistent, f32x2, acq/rel barrier) ----------------
// grid 128 = dir(2) x sent-tile(8 x 32 sents) x unit-tile(8 x 32 units), 256 threads
__global__ void __launch_bounds__(256) k_word_rec(
    const float* __restrict__ WhhF, const float* __restrict__ WhhB,
    const float* __restrict__ bhhF, const float* __restrict__ bhhB)
{
    extern __shared__ float sm[];
    float* ws  = sm;                 // [32 units][772]  (row = 3*256 gate-k + pad4)
    float* hs  = ws + 32 * 772;      // [32 sents][256]
    float* sbh = hs + 32 * 256;      // [96]
    const int blk = blockIdx.x;
    const int dir = blk >> 6;
    const int st  = (blk >> 3) & 7;
    const int ut  = blk & 7;
    const int u0  = ut * 32;
    const int grp = dir * 8 + st;
    const float* __restrict__ Whh = dir ? WhhB : WhhF;
    const float* __restrict__ bhh = dir ? bhhB : bhhF;
    const int tid = threadIdx.x;
    const int u = tid & 31, sg = tid >> 5;

    // weights: ws[uu*772 + g*256 + k] = Whh[(g*256 + u0 + uu)*256 + k]
    for (int idx = tid * 4; idx < 32 * 768; idx += 1024) {
        const int uu = idx / 768, rem = idx % 768;
        const int g = rem >> 8, k = rem & 255;
        *(float4*)&ws[uu * 772 + rem] =
            *(const float4*)&Whh[(size_t)(g * 256 + u0 + uu) * 256 + k];
    }
    if (tid < 96) sbh[tid] = bhh[(tid >> 5) * 256 + u0 + (tid & 31)];
    for (int i = tid; i < 32 * 256; i += 256) hs[i] = 0.0f;
    __syncthreads();

    const float* wp_ = ws + u * 772;
    const float bh_r = sbh[u], bh_z = sbh[32 + u], bh_n = sbh[64 + u];
    const int uc = u0 + u;

    for (int t = 0; t < 64; t++) {
        const int tt = dir ? (63 - t) : t;
        float xr[4], xz[4], xn[4];
#pragma unroll
        for (int j = 0; j < 4; j++) {
            const int s = st * 32 + sg * 4 + j;
            xr[j] = g_xg[dir][tt][s][uc];
            xz[j] = g_xg[dir][tt][s][256 + uc];
            xn[j] = g_xg[dir][tt][s][512 + uc];
        }
        ull acc2[3][4];
#pragma unroll
        for (int g = 0; g < 3; g++)
#pragma unroll
            for (int j = 0; j < 4; j++) acc2[g][j] = 0ull;

#pragma unroll 4
        for (int k = 0; k < 256; k += 4) {
            ulonglong2 w0 = *(const ulonglong2*)&wp_[k];
            ulonglong2 w1 = *(const ulonglong2*)&wp_[256 + k];
            ulonglong2 w2 = *(const ulonglong2*)&wp_[512 + k];
#pragma unroll
            for (int j = 0; j < 4; j++) {
                ulonglong2 h2 = *(const ulonglong2*)&hs[(sg * 4 + j) * 256 + k];
                fma2(acc2[0][j], w0.x, h2.x); fma2(acc2[0][j], w0.y, h2.y);
                fma2(acc2[1][j], w1.x, h2.x); fma2(acc2[1][j], w1.y, h2.y);
                fma2(acc2[2][j], w2.x, h2.x); fma2(acc2[2][j], w2.y, h2.y);
            }
        }
        const int par = (t + 1) & 1;
#pragma unroll
        for (int j = 0; j < 4; j++) {
            const int sl = sg * 4 + j;
            const int s  = st * 32 + sl;
            float2 f0 = asf2(acc2[0][j]), f1 = asf2(acc2[1][j]), f2 = asf2(acc2[2][j]);
            const float r = sigf(xr[j] + f0.x + f0.y + bh_r);
            const float z = sigf(xz[j] + f1.x + f1.y + bh_z);
            const float n = tanh_fast(xn[j] + r * (f2.x + f2.y + bh_n));
            const float hold = hs[sl * 256 + uc];
            const float hnew = (1.0f - z) * n + z * hold;
            __stcg(&g_hbuf[par][dir][s][uc], hnew);
            g_wordout[s][tt][dir * 256 + uc] = hnew;
        }
        __syncthreads();
        if (tid == 0) {
            bar_arrive(&g_bars[grp]);
            const unsigned tgt = 8u * (unsigned)(t + 1);
            while (bar_poll(&g_bars[grp]) < tgt) { }
        }
        __syncthreads();
        if (t < 63) {
            const float* src = &g_hbuf[par][dir][st * 32][0];
            for (int i = tid * 4; i < 32 * 256; i += 1024)
                *(float4*)&hs[i] = __ldcg((const float4*)(src + i));
            __syncthreads();
        }
    }
}

// ---------------- kernel 3: word attention pool -> sentence vectors ----------------
__global__ void __launch_bounds__(256) k_word_attn(
    const float* __restrict__ attw, const float* __restrict__ attb)
{
    __shared__ float sc[64];
    const int s = blockIdx.x;
    const int tid = threadIdx.x, wp = tid >> 5, ln = tid & 31;
    const float bb = attb[0];
    for (int w = wp; w < 64; w += 8) {
        const float* op = &g_wordout[s][w][0];
        float d = 0.0f;
#pragma unroll
        for (int i = 0; i < 4; i++) {
            float4 o = *(const float4*)&op[ln * 16 + i * 4];
            float4 a = *(const float4*)&attw[ln * 16 + i * 4];
            d += o.x * a.x + o.y * a.y + o.z * a.z + o.w * a.w;
        }
#pragma unroll
        for (int off = 16; off > 0; off >>= 1) d += __shfl_xor_sync(0xffffffffu, d, off);
        if (ln == 0) sc[w] = tanhf(d + bb);
    }
    __syncthreads();
    if (tid < 32) {
        float a0 = sc[tid], a1 = sc[tid + 32];
        float m = fmaxf(a0, a1);
#pragma unroll
        for (int off = 16; off > 0; off >>= 1) m = fmaxf(m, __shfl_xor_sync(0xffffffffu, m, off));
        float e0 = expf(a0 - m), e1 = expf(a1 - m);
        float ssum = e0 + e1;
#pragma unroll
        for (int off = 16; off > 0; off >>= 1) ssum += __shfl_xor_sync(0xffffffffu, ssum, off);
        sc[tid] = e0 / ssum; sc[tid + 32] = e1 / ssum;
    }
    __syncthreads();
    float acc0 = 0.0f, acc1 = 0.0f;
    for (int w = 0; w < 64; w++) {
        const float a = sc[w];
        acc0 += a * g_wordout[s][w][tid];
        acc1 += a * g_wordout[s][w][tid + 256];
    }
    g_sent[s][tid] = acc0;
    g_sent[s][tid + 256] = acc1;
}

// ---------------- kernel 4: sentence input gates (SGEMM K=512, f32x2) ----------------
// grid (24, 4)
__global__ void __launch_bounds__(256) k_sent_gates(
    const float* __restrict__ WihF, const float* __restrict__ WihB,
    const float* __restrict__ bihF, const float* __restrict__ bihB)
{
    __shared__ float As[64][36];
    __shared__ float Bs[64][36];
    const int s0  = blockIdx.y * 64;
    const int c0  = blockIdx.x * 64;
    const int dir = (c0 >= G3) ? 1 : 0;
    const int gc0 = c0 - dir * G3;
    const float* __restrict__ Wih = dir ? WihB : WihF;
    const float* __restrict__ bih = dir ? bihB : bihF;
    const int tid = threadIdx.x;
    const int tx = tid & 15, ty = tid >> 4;
    const int lr = tid >> 3, lk = (tid & 7) << 2;
    ull acc2[4][4];
#pragma unroll
    for (int i = 0; i < 4; i++)
#pragma unroll
        for (int j = 0; j < 4; j++) acc2[i][j] = 0ull;

    for (int k0 = 0; k0 < 512; k0 += 32) {
#pragma unroll
        for (int p = 0; p < 2; p++) {
            const int r = p * 32 + lr;
            *(float4*)&As[r][lk] = *(const float4*)&g_sent[s0 + r][k0 + lk];
            *(float4*)&Bs[r][lk] = *(const float4*)&Wih[(size_t)(gc0 + r) * 512 + k0 + lk];
        }
        __syncthreads();
#pragma unroll
        for (int k = 0; k < 32; k += 4) {
            ulonglong2 a_[4], b_[4];
#pragma unroll
            for (int i = 0; i < 4; i++) a_[i] = *(const ulonglong2*)&As[ty * 4 + i][k];
#pragma unroll
            for (int j = 0; j < 4; j++) b_[j] = *(const ulonglong2*)&Bs[tx + 16 * j][k];
#pragma unroll
            for (int i = 0; i < 4; i++)
#pragma unroll
                for (int j = 0; j < 4; j++) {
                    fma2(acc2[i][j], a_[i].x, b_[j].x);
                    fma2(acc2[i][j], a_[i].y, b_[j].y);
                }
        }
        __syncthreads();
    }
#pragma unroll
    for (int j = 0; j < 4; j++) {
        const int cgl = gc0 + tx + 16 * j;
        const float bj = bih[cgl];
#pragma unroll
        for (int i = 0; i < 4; i++) {
            float2 f = asf2(acc2[i][j]);
            g_sxg[dir][s0 + ty * 4 + i][cgl] = f.x + f.y + bj;
        }
    }
}

// ---------------- kernel 5: sentence recurrence (persistent, f32x2) ----------------
// grid 16 = dir(2) x unit-tile(8 x 32 units), 192 threads
__global__ void __launch_bounds__(192) k_sent_rec(
    const float* __restrict__ WhhF, const float* __restrict__ WhhB,
    const float* __restrict__ bhhF, const float* __restrict__ bhhB)
{
    extern __shared__ float sm2[];
    float* wsm = sm2;                 // 192 half-rows x 132 (padded)
    float* hsh = wsm + 192 * 132;     // [256]
    float* gv  = hsh + 256;           // [96]
    const int dir = blockIdx.x >> 3;
    const int ut  = blockIdx.x & 7;
    const int u0  = ut * 32;
    const int grp = 16 + dir;
    const float* __restrict__ Whh = dir ? WhhB : WhhF;
    const float* __restrict__ bhh = dir ? bhhB : bhhF;
    const int tid = threadIdx.x;

    for (int idx = tid; idx < 96 * 256; idx += 192) {
        const int r = idx >> 8, k = idx & 255;
        const int row_g = (r >> 5) * 256 + u0 + (r & 31);
        wsm[(r * 2 + (k >> 7)) * 132 + (k & 127)] = Whh[(size_t)row_g * 256 + k];
    }
    for (int k = tid; k < 256; k += 192) hsh[k] = 0.0f;
    __syncthreads();

    const int r = tid >> 1, half = tid & 1;
    const int row_g = (r >> 5) * 256 + u0 + (r & 31);
    const float bh = bhh[row_g];
    const float* wp = &wsm[tid * 132];
    const int hbase = half * 128;

    for (int t = 0; t < 256; t++) {
        const int tt = dir ? (255 - t) : t;
        float xr = 0.0f, xz = 0.0f, xn = 0.0f, hold = 0.0f;
        if (tid < 32) {
            const int u = u0 + tid;
            xr = g_sxg[dir][tt][u];
            xz = g_sxg[dir][tt][256 + u];
            xn = g_sxg[dir][tt][512 + u];
            hold = hsh[u];
        }
        ull acc2 = 0ull;
        // 128 elements per half-row: 32 x ulonglong2 (4 floats each), stride 4
#pragma unroll
        for (int i = 0; i < 32; i++) {
            ulonglong2 h2 = *(const ulonglong2*)&hsh[hbase + i * 4];
            ulonglong2 w2 = *(const ulonglong2*)&wp[i * 4];
            fma2(acc2, h2.x, w2.x);
            fma2(acc2, h2.y, w2.y);
        }
        float2 fa = asf2(acc2);
        float acc = fa.x + fa.y;
        acc += __shfl_xor_sync(0xffffffffu, acc, 1);
        if (half == 0) gv[r] = acc + bh;
        __syncthreads();
        const int par = (t + 1) & 1;
        if (tid < 32) {
            const int u = u0 + tid;
            const float rr = sigf(xr + gv[tid]);
            const float zz = sigf(xz + gv[32 + tid]);
            const float nn = tanh_fast(xn + rr * gv[64 + tid]);
            const float hnew = (1.0f - zz) * nn + zz * hold;
            __stcg(&g_shbuf[par][dir][u], hnew);
            g_sentout[tt][dir * 256 + u] = hnew;
        }
        __syncthreads();
        if (tid == 0) {
            bar_arrive(&g_bars[grp]);
            const unsigned tgt = 8u * (unsigned)(t + 1);
            while (bar_poll(&g_bars[grp]) < tgt) { }
        }
        __syncthreads();
        if (t < 255) {
            for (int k = tid; k < 256; k += 192) hsh[k] = __ldcg(&g_shbuf[par][dir][k]);
            __syncthreads();
        }
    }
}

// ---------------- kernel 6: sentence attention + classifier + softmax ----------------
__global__ void __launch_bounds__(256) k_doc(
    const float* __restrict__ attw, const float* __restrict__ attb,
    const float* __restrict__ clsW, const float* __restrict__ clsB,
    float* __restrict__ out)
{
    __shared__ float sc[256];
    __shared__ float red[8];
    __shared__ float docv[512];
    __shared__ float lg[10];
    const int tid = threadIdx.x, wp = tid >> 5, ln = tid & 31;
    const float bb = attb[0];
    for (int s = wp; s < 256; s += 8) {
        const float* op = &g_sentout[s][0];
        float d = 0.0f;
#pragma unroll
        for (int i = 0; i < 4; i++) {
            float4 o = *(const float4*)&op[ln * 16 + i * 4];
            float4 a = *(const float4*)&attw[ln * 16 + i * 4];
            d += o.x * a.x + o.y * a.y + o.z * a.z + o.w * a.w;
        }
#pragma unroll
        for (int off = 16; off > 0; off >>= 1) d += __shfl_xor_sync(0xffffffffu, d, off);
        if (ln == 0) sc[s] = tanhf(d + bb);
    }
    __syncthreads();
    float v = sc[tid];
    float m = v;
#pragma unroll
    for (int off = 16; off > 0; off >>= 1) m = fmaxf(m, __shfl_xor_sync(0xffffffffu, m, off));
    if (ln == 0) red[wp] = m;
    __syncthreads();
    if (tid < 8) {
        float mm = red[tid];
#pragma unroll
        for (int off = 4; off > 0; off >>= 1) mm = fmaxf(mm, __shfl_xor_sync(0xffu, mm, off));
        red[tid] = mm;
    }
    __syncthreads();
    const float gm = red[0];
    float e = expf(v - gm);
    float ssum = e;
#pragma unroll
    for (int off = 16; off > 0; off >>= 1) ssum += __shfl_xor_sync(0xffffffffu, ssum, off);
    __syncthreads();
    if (ln == 0) red[wp] = ssum;
    __syncthreads();
    if (tid < 8) {
        float s2 = red[tid];
#pragma unroll
        for (int off = 4; off > 0; off >>= 1) s2 += __shfl_xor_sync(0xffu, s2, off);
        red[tid] = s2;
    }
    __syncthreads();
    const float tot = red[0];
    sc[tid] = e / tot;
    __syncthreads();
    float a0 = 0.0f, a1 = 0.0f;
    for (int s = 0; s < 256; s++) {
        const float a = sc[s];
        a0 += a * g_sentout[s][tid];
        a1 += a * g_sentout[s][tid + 256];
    }
    docv[tid] = a0; docv[tid + 256] = a1;
    __syncthreads();
    for (int o = wp; o < 10; o += 8) {
        const float* wr = &clsW[o * 512];
        float d = 0.0f;
#pragma unroll
        for (int i = 0; i < 4; i++) {
            float4 x = *(const float4*)&docv[ln * 16 + i * 4];
            float4 w = *(const float4*)&wr[ln * 16 + i * 4];
            d += x.x * w.x + x.y * w.y + x.z * w.z + x.w * w.w;
        }
#pragma unroll
        for (int off = 16; off > 0; off >>= 1) d += __shfl_xor_sync(0xffffffffu, d, off);
        if (ln == 0) lg[o] = d + clsB[o];
    }
    __syncthreads();
    if (tid == 0) {
        float mm = lg[0];
        for (int i = 1; i < 10; i++) mm = fmaxf(mm, lg[i]);
        float s2 = 0.0f;
        float ee[10];
        for (int i = 0; i < 10; i++) { ee[i] = expf(lg[i] - mm); s2 += ee[i]; }
        for (int i = 0; i < 10; i++) out[i] = ee[i] / s2;
    }
}

// ---------------- launch ----------------
extern "C" void kernel_launch(void* const* d_in, const int* in_sizes, int n_in,
                              void* d_out, int out_size) {
    const int*   toks  = (const int*)d_in[0];
    const float* emb   = (const float*)d_in[1];
    const float* wWihF = (const float*)d_in[2];
    const float* wWhhF = (const float*)d_in[3];
    const float* wBihF = (const float*)d_in[4];
    const float* wBhhF = (const float*)d_in[5];
    const float* wWihB = (const float*)d_in[6];
    const float* wWhhB = (const float*)d_in[7];
    const float* wBihB = (const float*)d_in[8];
    const float* wBhhB = (const float*)d_in[9];
    const float* sWihF = (const float*)d_in[10];
    const float* sWhhF = (const float*)d_in[11];
    const float* sBihF = (const float*)d_in[12];
    const float* sBhhF = (const float*)d_in[13];
    const float* sWihB = (const float*)d_in[14];
    const float* sWhhB = (const float*)d_in[15];
    const float* sBihB = (const float*)d_in[16];
    const float* sBhhB = (const float*)d_in[17];
    const float* wAttW = (const float*)d_in[18];
    const float* wAttB = (const float*)d_in[19];
    const float* sAttW = (const float*)d_in[20];
    const float* sAttB = (const float*)d_in[21];
    const float* clsW  = (const float*)d_in[22];
    const float* clsB  = (const float*)d_in[23];
    float* out = (float*)d_out;

    const int WREC_SMEM = (32 * 772 + 32 * 256 + 96) * 4;   // 131968
    const int SREC_SMEM = (192 * 132 + 256 + 96) * 4;       // 102784
    cudaFuncSetAttribute(k_word_rec, cudaFuncAttributeMaxDynamicSharedMemorySize, WREC_SMEM);
    cudaFuncSetAttribute(k_sent_rec, cudaFuncAttributeMaxDynamicSharedMemorySize, SREC_SMEM);

    k_zero_bars<<<1, 32>>>();
    dim3 g1(24, 256);
    k_word_gates<<<g1, 256>>>(toks, emb, wWihF, wWihB, wBihF, wBihB);
    k_word_rec<<<128, 256, WREC_SMEM>>>(wWhhF, wWhhB, wBhhF, wBhhB);
    k_word_attn<<<256, 256>>>(wAttW, wAttB);
    dim3 g2(24, 4);
    k_sent_gates<<<g2, 256>>>(sWihF, sWihB, sBihF, sBihB);
    k_sent_rec<<<16, 192, SREC_SMEM>>>(sWhhF, sWhhB, sBhhF, sBhhB);
    k_doc<<<1, 256>>>(sAttW, sAttB, clsW, clsB, out);
}

// round 7
// speedup vs baseline: 1.3476x; 1.1379x over previous
#include <cuda_runtime.h>
#include <math.h>
#include <stdint.h>

// HAN: S=256 sentences x W=64 words, E=256, HW=HS=256, C=10
#define SN 256
#define WN 64
#define EN 256
#define HWD 256
#define G3 768

typedef unsigned long long ull;

// ---------------- static device scratch ----------------
__device__ float g_xg[2][WN][SN][G3];      // word input gates, time-major
__device__ float g_wordout[SN][WN][512];   // word BiGRU outputs (F 0..255, B 256..511)
__device__ float g_sent[SN][512];          // sentence vectors
__device__ float g_sxg[2][SN][G3];         // sentence input gates
__device__ float g_sentout[SN][512];       // sentence BiGRU outputs
__device__ float g_hbuf[2][2][SN][HWD];    // word rec h exchange [parity][dir][s][u]
__device__ float g_shbuf[2][2][HWD];       // sent rec h exchange [parity][dir][u]
__device__ unsigned g_bars[32];            // barrier counters

// ---------------- helpers ----------------
__device__ __forceinline__ void fma2(ull& d, ull a, ull b) {
    asm("fma.rn.f32x2 %0, %1, %2, %0;" : "+l"(d) : "l"(a), "l"(b));
}
__device__ __forceinline__ float2 asf2(ull v) {
    float2 r; asm("mov.b64 {%0, %1}, %2;" : "=f"(r.x), "=f"(r.y) : "l"(v)); return r;
}
__device__ __forceinline__ float sigf(float x) {
    return __fdividef(1.0f, 1.0f + __expf(-x));
}
__device__ __forceinline__ float tanh_fast(float x) {
    float e = __expf(-2.0f * x);
    return (1.0f - e) * __fdividef(1.0f, 1.0f + e);
}
__device__ __forceinline__ void bar_arrive(unsigned* p) {
    asm volatile("red.release.gpu.add.u32 [%0], %1;" :: "l"(p), "r"(1u) : "memory");
}
__device__ __forceinline__ unsigned bar_poll(const unsigned* p) {
    unsigned v;
    asm volatile("ld.acquire.gpu.u32 %0, [%1];" : "=r"(v) : "l"(p) : "memory");
    return v;
}

__global__ void k_zero_bars() {
    if (threadIdx.x < 32) g_bars[threadIdx.x] = 0u;
}

// ---------------- kernel 1: word input gates (gathered SGEMM, f32x2) ----------------
// grid (24, 256): 24 col tiles of 64 (F 0..767, B 768..1535), one sentence per blockIdx.y
__global__ void __launch_bounds__(256) k_word_gates(
    const int* __restrict__ toks, const float* __restrict__ emb,
    const float* __restrict__ WihF, const float* __restrict__ WihB,
    const float* __restrict__ bihF, const float* __restrict__ bihB)
{
    __shared__ float As[64][36];   // [row][k0..31 + pad]
    __shared__ float Bs[64][36];
    __shared__ int stok[64];
    const int s   = blockIdx.y;
    const int c0  = blockIdx.x * 64;
    const int dir = (c0 >= G3) ? 1 : 0;
    const int gc0 = c0 - dir * G3;
    const float* __restrict__ Wih = dir ? WihB : WihF;
    const float* __restrict__ bih = dir ? bihB : bihF;
    const int tid = threadIdx.x;
    if (tid < 64) stok[tid] = toks[s * WN + tid];
    __syncthreads();
    const int tx = tid & 15, ty = tid >> 4;
    const int lr = tid >> 3, lk = (tid & 7) << 2;
    ull acc2[4][4];
#pragma unroll
    for (int i = 0; i < 4; i++)
#pragma unroll
        for (int j = 0; j < 4; j++) acc2[i][j] = 0ull;

    for (int k0 = 0; k0 < EN; k0 += 32) {
#pragma unroll
        for (int p = 0; p < 2; p++) {
            const int r = p * 32 + lr;
            *(float4*)&As[r][lk] = *(const float4*)&emb[(size_t)stok[r] * EN + k0 + lk];
            *(float4*)&Bs[r][lk] = *(const float4*)&Wih[(size_t)(gc0 + r) * EN + k0 + lk];
        }
        __syncthreads();
#pragma unroll
        for (int k = 0; k < 32; k += 4) {
            ulonglong2 a_[4], b_[4];
#pragma unroll
            for (int i = 0; i < 4; i++) a_[i] = *(const ulonglong2*)&As[ty * 4 + i][k];
#pragma unroll
            for (int j = 0; j < 4; j++) b_[j] = *(const ulonglong2*)&Bs[tx + 16 * j][k];
#pragma unroll
            for (int i = 0; i < 4; i++)
#pragma unroll
                for (int j = 0; j < 4; j++) {
                    fma2(acc2[i][j], a_[i].x, b_[j].x);
                    fma2(acc2[i][j], a_[i].y, b_[j].y);
                }
        }
        __syncthreads();
    }
#pragma unroll
    for (int j = 0; j < 4; j++) {
        const int cgl = gc0 + tx + 16 * j;
        const float bj = bih[cgl];
#pragma unroll
        for (int i = 0; i < 4; i++) {
            float2 f = asf2(acc2[i][j]);
            g_xg[dir][ty * 4 + i][s][cgl] = f.x + f.y + bj;
        }
    }
}

// ---------------- kernel 2: word recurrence (persistent, f32x2, K-split mapping) ----------------
// grid 128 = dir(2) x sent-tile(8 x 32 sents) x unit-tile(8 x 32 units), 256 threads
// thread map: u = tid&31 (unit), sq = (tid>>5)&3 (8-sent quad), kh = tid>>7 (K half)
__global__ void __launch_bounds__(256) k_word_rec(
    const float* __restrict__ WhhF, const float* __restrict__ WhhB,
    const float* __restrict__ bhhF, const float* __restrict__ bhhB)
{
    extern __shared__ float sm[];
    float* ws  = sm;                 // [2 kh][32 u][388]  (row = 3*128 gate-khalf + pad4)
    float* hs  = ws + 2 * 32 * 388;  // [32 sents][256]
    float* cb  = hs + 32 * 256;      // [128][25] khalf-1 partials
    float* sbh = cb + 128 * 25;      // [96]
    const int blk = blockIdx.x;
    const int dir = blk >> 6;
    const int st  = (blk >> 3) & 7;
    const int ut  = blk & 7;
    const int u0  = ut * 32;
    const int grp = dir * 8 + st;
    const float* __restrict__ Whh = dir ? WhhB : WhhF;
    const float* __restrict__ bhh = dir ? bhhB : bhhF;
    const int tid = threadIdx.x;
    const int u  = tid & 31;
    const int sq = (tid >> 5) & 3;
    const int kh = tid >> 7;

    // weights: ws[(kh*32+uu)*388 + g*128 + kk] = Whh[(g*256+u0+uu)*256 + kh*128 + kk]
    for (int idx = tid * 4; idx < 2 * 32 * 384; idx += 1024) {
        const int khh = idx / 12288;
        const int r2  = idx % 12288;
        const int uu  = r2 / 384;
        const int rem = r2 % 384;
        const int g = rem >> 7, kk = rem & 127;
        *(float4*)&ws[(khh * 32 + uu) * 388 + rem] =
            *(const float4*)&Whh[(size_t)(g * 256 + u0 + uu) * 256 + khh * 128 + kk];
    }
    if (tid < 96) sbh[tid] = bhh[(tid >> 5) * 256 + u0 + (tid & 31)];
    for (int i = tid; i < 32 * 256; i += 256) hs[i] = 0.0f;
    __syncthreads();

    const float* wku = &ws[(kh * 32 + u) * 388];
    const float bh_r = sbh[u], bh_z = sbh[32 + u], bh_n = sbh[64 + u];
    const int uc = u0 + u;
    const int kb = kh * 128;

    for (int t = 0; t < 64; t++) {
        const int tt = dir ? (63 - t) : t;
        float xr[8], xz[8], xn[8], hold[8];
        if (kh == 0) {
#pragma unroll
            for (int j = 0; j < 8; j++) {
                const int s = st * 32 + sq * 8 + j;
                xr[j]   = g_xg[dir][tt][s][uc];
                xz[j]   = g_xg[dir][tt][s][256 + uc];
                xn[j]   = g_xg[dir][tt][s][512 + uc];
                hold[j] = hs[(sq * 8 + j) * 256 + uc];
            }
        }
        ull acc[3][8];
#pragma unroll
        for (int g = 0; g < 3; g++)
#pragma unroll
            for (int j = 0; j < 8; j++) acc[g][j] = 0ull;

#pragma unroll 4
        for (int kk = 0; kk < 128; kk += 4) {
            ulonglong2 w0 = *(const ulonglong2*)&wku[kk];
            ulonglong2 w1 = *(const ulonglong2*)&wku[128 + kk];
            ulonglong2 w2 = *(const ulonglong2*)&wku[256 + kk];
#pragma unroll
            for (int j = 0; j < 8; j++) {
                ulonglong2 h2 = *(const ulonglong2*)&hs[(sq * 8 + j) * 256 + kb + kk];
                fma2(acc[0][j], w0.x, h2.x); fma2(acc[0][j], w0.y, h2.y);
                fma2(acc[1][j], w1.x, h2.x); fma2(acc[1][j], w1.y, h2.y);
                fma2(acc[2][j], w2.x, h2.x); fma2(acc[2][j], w2.y, h2.y);
            }
        }
        float p[24];
#pragma unroll
        for (int g = 0; g < 3; g++)
#pragma unroll
            for (int j = 0; j < 8; j++) {
                float2 f = asf2(acc[g][j]);
                p[g * 8 + j] = f.x + f.y;
            }
        if (kh) {
            float* row = &cb[(sq * 32 + u) * 25];
#pragma unroll
            for (int i = 0; i < 24; i++) row[i] = p[i];
        }
        __syncthreads();
        const int par = (t + 1) & 1;
        if (kh == 0) {
            const float* row = &cb[(sq * 32 + u) * 25];
#pragma unroll
            for (int i = 0; i < 24; i++) p[i] += row[i];
#pragma unroll
            for (int j = 0; j < 8; j++) {
                const int s = st * 32 + sq * 8 + j;
                const float r = sigf(xr[j] + p[j] + bh_r);
                const float z = sigf(xz[j] + p[8 + j] + bh_z);
                const float n = tanh_fast(xn[j] + r * (p[16 + j] + bh_n));
                const float hnew = (1.0f - z) * n + z * hold[j];
                __stcg(&g_hbuf[par][dir][s][uc], hnew);
                g_wordout[s][tt][dir * 256 + uc] = hnew;
            }
        }
        __syncthreads();
        if (tid == 0) {
            bar_arrive(&g_bars[grp]);
            const unsigned tgt = 8u * (unsigned)(t + 1);
            while (bar_poll(&g_bars[grp]) < tgt) { }
        }
        __syncthreads();
        if (t < 63) {
            const float* src = &g_hbuf[par][dir][st * 32][0];
            for (int i = tid * 4; i < 32 * 256; i += 1024)
                *(float4*)&hs[i] = __ldcg((const float4*)(src + i));
            __syncthreads();
        }
    }
}

// ---------------- kernel 3: word attention pool -> sentence vectors ----------------
__global__ void __launch_bounds__(256) k_word_attn(
    const float* __restrict__ attw, const float* __restrict__ attb)
{
    __shared__ float sc[64];
    const int s = blockIdx.x;
    const int tid = threadIdx.x, wp = tid >> 5, ln = tid & 31;
    const float bb = attb[0];
    for (int w = wp; w < 64; w += 8) {
        const float* op = &g_wordout[s][w][0];
        float d = 0.0f;
#pragma unroll
        for (int i = 0; i < 4; i++) {
            float4 o = *(const float4*)&op[ln * 16 + i * 4];
            float4 a = *(const float4*)&attw[ln * 16 + i * 4];
            d += o.x * a.x + o.y * a.y + o.z * a.z + o.w * a.w;
        }
#pragma unroll
        for (int off = 16; off > 0; off >>= 1) d += __shfl_xor_sync(0xffffffffu, d, off);
        if (ln == 0) sc[w] = tanhf(d + bb);
    }
    __syncthreads();
    if (tid < 32) {
        float a0 = sc[tid], a1 = sc[tid + 32];
        float m = fmaxf(a0, a1);
#pragma unroll
        for (int off = 16; off > 0; off >>= 1) m = fmaxf(m, __shfl_xor_sync(0xffffffffu, m, off));
        float e0 = expf(a0 - m), e1 = expf(a1 - m);
        float ssum = e0 + e1;
#pragma unroll
        for (int off = 16; off > 0; off >>= 1) ssum += __shfl_xor_sync(0xffffffffu, ssum, off);
        sc[tid] = e0 / ssum; sc[tid + 32] = e1 / ssum;
    }
    __syncthreads();
    float acc0 = 0.0f, acc1 = 0.0f;
    for (int w = 0; w < 64; w++) {
        const float a = sc[w];
        acc0 += a * g_wordout[s][w][tid];
        acc1 += a * g_wordout[s][w][tid + 256];
    }
    g_sent[s][tid] = acc0;
    g_sent[s][tid + 256] = acc1;
}

// ---------------- kernel 4: sentence input gates (SGEMM K=512, f32x2) ----------------
// grid (24, 4)
__global__ void __launch_bounds__(256) k_sent_gates(
    const float* __restrict__ WihF, const float* __restrict__ WihB,
    const float* __restrict__ bihF, const float* __restrict__ bihB)
{
    __shared__ float As[64][36];
    __shared__ float Bs[64][36];
    const int s0  = blockIdx.y * 64;
    const int c0  = blockIdx.x * 64;
    const int dir = (c0 >= G3) ? 1 : 0;
    const int gc0 = c0 - dir * G3;
    const float* __restrict__ Wih = dir ? WihB : WihF;
    const float* __restrict__ bih = dir ? bihB : bihF;
    const int tid = threadIdx.x;
    const int tx = tid & 15, ty = tid >> 4;
    const int lr = tid >> 3, lk = (tid & 7) << 2;
    ull acc2[4][4];
#pragma unroll
    for (int i = 0; i < 4; i++)
#pragma unroll
        for (int j = 0; j < 4; j++) acc2[i][j] = 0ull;

    for (int k0 = 0; k0 < 512; k0 += 32) {
#pragma unroll
        for (int p = 0; p < 2; p++) {
            const int r = p * 32 + lr;
            *(float4*)&As[r][lk] = *(const float4*)&g_sent[s0 + r][k0 + lk];
            *(float4*)&Bs[r][lk] = *(const float4*)&Wih[(size_t)(gc0 + r) * 512 + k0 + lk];
        }
        __syncthreads();
#pragma unroll
        for (int k = 0; k < 32; k += 4) {
            ulonglong2 a_[4], b_[4];
#pragma unroll
            for (int i = 0; i < 4; i++) a_[i] = *(const ulonglong2*)&As[ty * 4 + i][k];
#pragma unroll
            for (int j = 0; j < 4; j++) b_[j] = *(const ulonglong2*)&Bs[tx + 16 * j][k];
#pragma unroll
            for (int i = 0; i < 4; i++)
#pragma unroll
                for (int j = 0; j < 4; j++) {
                    fma2(acc2[i][j], a_[i].x, b_[j].x);
                    fma2(acc2[i][j], a_[i].y, b_[j].y);
                }
        }
        __syncthreads();
    }
#pragma unroll
    for (int j = 0; j < 4; j++) {
        const int cgl = gc0 + tx + 16 * j;
        const float bj = bih[cgl];
#pragma unroll
        for (int i = 0; i < 4; i++) {
            float2 f = asf2(acc2[i][j]);
            g_sxg[dir][s0 + ty * 4 + i][cgl] = f.x + f.y + bj;
        }
    }
}

// ---------------- kernel 5: sentence recurrence (persistent, f32x2, 8-CTA cluster) ----------------
// grid 16 = dir(2) x unit-tile(8 x 32 units) = 2 clusters of 8, 192 threads
__global__ void __launch_bounds__(192) __cluster_dims__(8, 1, 1) k_sent_rec(
    const float* __restrict__ WhhF, const float* __restrict__ WhhB,
    const float* __restrict__ bhhF, const float* __restrict__ bhhB)
{
    extern __shared__ float sm2[];
    float* wsm = sm2;                 // 192 half-rows x 132 (padded)
    float* hsh = wsm + 192 * 132;     // [256]
    float* gv  = hsh + 256;           // [96]
    const int dir = blockIdx.x >> 3;
    const int ut  = blockIdx.x & 7;
    const int u0  = ut * 32;
    const float* __restrict__ Whh = dir ? WhhB : WhhF;
    const float* __restrict__ bhh = dir ? bhhB : bhhF;
    const int tid = threadIdx.x;

    for (int idx = tid; idx < 96 * 256; idx += 192) {
        const int r = idx >> 8, k = idx & 255;
        const int row_g = (r >> 5) * 256 + u0 + (r & 31);
        wsm[(r * 2 + (k >> 7)) * 132 + (k & 127)] = Whh[(size_t)row_g * 256 + k];
    }
    for (int k = tid; k < 256; k += 192) hsh[k] = 0.0f;
    __syncthreads();
    // all cluster CTAs ready before first step
    asm volatile("barrier.cluster.arrive.aligned;" ::: "memory");
    asm volatile("barrier.cluster.wait.aligned;" ::: "memory");

    const int r = tid >> 1, half = tid & 1;
    const int row_g = (r >> 5) * 256 + u0 + (r & 31);
    const float bh = bhh[row_g];
    const float* wp = &wsm[tid * 132];
    const int hbase = half * 128;

    for (int t = 0; t < 256; t++) {
        const int tt = dir ? (255 - t) : t;
        float xr = 0.0f, xz = 0.0f, xn = 0.0f, hold = 0.0f;
        if (tid < 32) {
            const int u = u0 + tid;
            xr = g_sxg[dir][tt][u];
            xz = g_sxg[dir][tt][256 + u];
            xn = g_sxg[dir][tt][512 + u];
            hold = hsh[u];
        }
        ull acc2 = 0ull;
        // 128 elements per half-row: 32 x ulonglong2 (4 floats each), stride 4
#pragma unroll
        for (int i = 0; i < 32; i++) {
            ulonglong2 h2 = *(const ulonglong2*)&hsh[hbase + i * 4];
            ulonglong2 w2 = *(const ulonglong2*)&wp[i * 4];
            fma2(acc2, h2.x, w2.x);
            fma2(acc2, h2.y, w2.y);
        }
        float2 fa = asf2(acc2);
        float acc = fa.x + fa.y;
        acc += __shfl_xor_sync(0xffffffffu, acc, 1);
        if (half == 0) gv[r] = acc + bh;
        __syncthreads();
        const int par = (t + 1) & 1;
        if (tid < 32) {
            const int u = u0 + tid;
            const float rr = sigf(xr + gv[tid]);
            const float zz = sigf(xz + gv[32 + tid]);
            const float nn = tanh_fast(xn + rr * gv[64 + tid]);
            const float hnew = (1.0f - zz) * nn + zz * hold;
            __stcg(&g_shbuf[par][dir][u], hnew);
            g_sentout[tt][dir * 256 + u] = hnew;
        }
        // cluster barrier: arrive releases each thread's prior stores (cluster scope
        // covers global); wait acquires -> peers' ldcg reads below see fresh h
        asm volatile("barrier.cluster.arrive.aligned;" ::: "memory");
        asm volatile("barrier.cluster.wait.aligned;" ::: "memory");
        if (t < 255) {
            for (int k = tid; k < 256; k += 192) hsh[k] = __ldcg(&g_shbuf[par][dir][k]);
            __syncthreads();
        }
    }
}

// ---------------- kernel 6: sentence attention + classifier + softmax ----------------
__global__ void __launch_bounds__(256) k_doc(
    const float* __restrict__ attw, const float* __restrict__ attb,
    const float* __restrict__ clsW, const float* __restrict__ clsB,
    float* __restrict__ out)
{
    __shared__ float sc[256];
    __shared__ float red[8];
    __shared__ float docv[512];
    __shared__ float lg[10];
    const int tid = threadIdx.x, wp = tid >> 5, ln = tid & 31;
    const float bb = attb[0];
    for (int s = wp; s < 256; s += 8) {
        const float* op = &g_sentout[s][0];
        float d = 0.0f;
#pragma unroll
        for (int i = 0; i < 4; i++) {
            float4 o = *(const float4*)&op[ln * 16 + i * 4];
            float4 a = *(const float4*)&attw[ln * 16 + i * 4];
            d += o.x * a.x + o.y * a.y + o.z * a.z + o.w * a.w;
        }
#pragma unroll
        for (int off = 16; off > 0; off >>= 1) d += __shfl_xor_sync(0xffffffffu, d, off);
        if (ln == 0) sc[s] = tanhf(d + bb);
    }
    __syncthreads();
    float v = sc[tid];
    float m = v;
#pragma unroll
    for (int off = 16; off > 0; off >>= 1) m = fmaxf(m, __shfl_xor_sync(0xffffffffu, m, off));
    if (ln == 0) red[wp] = m;
    __syncthreads();
    if (tid < 8) {
        float mm = red[tid];
#pragma unroll
        for (int off = 4; off > 0; off >>= 1) mm = fmaxf(mm, __shfl_xor_sync(0xffu, mm, off));
        red[tid] = mm;
    }
    __syncthreads();
    const float gm = red[0];
    float e = expf(v - gm);
    float ssum = e;
#pragma unroll
    for (int off = 16; off > 0; off >>= 1) ssum += __shfl_xor_sync(0xffffffffu, ssum, off);
    __syncthreads();
    if (ln == 0) red[wp] = ssum;
    __syncthreads();
    if (tid < 8) {
        float s2 = red[tid];
#pragma unroll
        for (int off = 4; off > 0; off >>= 1) s2 += __shfl_xor_sync(0xffu, s2, off);
        red[tid] = s2;
    }
    __syncthreads();
    const float tot = red[0];
    sc[tid] = e / tot;
    __syncthreads();
    float a0 = 0.0f, a1 = 0.0f;
    for (int s = 0; s < 256; s++) {
        const float a = sc[s];
        a0 += a * g_sentout[s][tid];
        a1 += a * g_sentout[s][tid + 256];
    }
    docv[tid] = a0; docv[tid + 256] = a1;
    __syncthreads();
    for (int o = wp; o < 10; o += 8) {
        const float* wr = &clsW[o * 512];
        float d = 0.0f;
#pragma unroll
        for (int i = 0; i < 4; i++) {
            float4 x = *(const float4*)&docv[ln * 16 + i * 4];
            float4 w = *(const float4*)&wr[ln * 16 + i * 4];
            d += x.x * w.x + x.y * w.y + x.z * w.z + x.w * w.w;
        }
#pragma unroll
        for (int off = 16; off > 0; off >>= 1) d += __shfl_xor_sync(0xffffffffu, d, off);
        if (ln == 0) lg[o] = d + clsB[o];
    }
    __syncthreads();
    if (tid == 0) {
        float mm = lg[0];
        for (int i = 1; i < 10; i++) mm = fmaxf(mm, lg[i]);
        float s2 = 0.0f;
        float ee[10];
        for (int i = 0; i < 10; i++) { ee[i] = expf(lg[i] - mm); s2 += ee[i]; }
        for (int i = 0; i < 10; i++) out[i] = ee[i] / s2;
    }
}

// ---------------- launch ----------------
extern "C" void kernel_launch(void* const* d_in, const int* in_sizes, int n_in,
                              void* d_out, int out_size) {
    const int*   toks  = (const int*)d_in[0];
    const float* emb   = (const float*)d_in[1];
    const float* wWihF = (const float*)d_in[2];
    const float* wWhhF = (const float*)d_in[3];
    const float* wBihF = (const float*)d_in[4];
    const float* wBhhF = (const float*)d_in[5];
    const float* wWihB = (const float*)d_in[6];
    const float* wWhhB = (const float*)d_in[7];
    const float* wBihB = (const float*)d_in[8];
    const float* wBhhB = (const float*)d_in[9];
    const float* sWihF = (const float*)d_in[10];
    const float* sWhhF = (const float*)d_in[11];
    const float* sBihF = (const float*)d_in[12];
    const float* sBhhF = (const float*)d_in[13];
    const float* sWihB = (const float*)d_in[14];
    const float* sWhhB = (const float*)d_in[15];
    const float* sBihB = (const float*)d_in[16];
    const float* sBhhB = (const float*)d_in[17];
    const float* wAttW = (const float*)d_in[18];
    const float* wAttB = (const float*)d_in[19];
    const float* sAttW = (const float*)d_in[20];
    const float* sAttB = (const float*)d_in[21];
    const float* clsW  = (const float*)d_in[22];
    const float* clsB  = (const float*)d_in[23];
    float* out = (float*)d_out;

    const int WREC_SMEM = (2 * 32 * 388 + 32 * 256 + 128 * 25 + 96) * 4;  // 145280
    const int SREC_SMEM = (192 * 132 + 256 + 96) * 4;                     // 102784
    cudaFuncSetAttribute(k_word_rec, cudaFuncAttributeMaxDynamicSharedMemorySize, WREC_SMEM);
    cudaFuncSetAttribute(k_sent_rec, cudaFuncAttributeMaxDynamicSharedMemorySize, SREC_SMEM);

    k_zero_bars<<<1, 32>>>();
    k_zero_bars<<<1, 32>>>();   // dummy: shifts k_word_rec to the ncu-captured launch slot
    dim3 g1(24, 256);
    k_word_gates<<<g1, 256>>>(toks, emb, wWihF, wWihB, wBihF, wBihB);
    k_word_rec<<<128, 256, WREC_SMEM>>>(wWhhF, wWhhB, wBhhF, wBhhB);
    k_word_attn<<<256, 256>>>(wAttW, wAttB);
    dim3 g2(24, 4);
    k_sent_gates<<<g2, 256>>>(sWihF, sWihB, sBihF, sBihB);
    k_sent_rec<<<16, 192, SREC_SMEM>>>(sWhhF, sWhhB, sBhhF, sBhhB);
    k_doc<<<1, 256>>>(sAttW, sAttB, clsW, clsB, out);
}

// round 8
// speedup vs baseline: 1.4048x; 1.0424x over previous
#include <cuda_runtime.h>
#include <math.h>
#include <stdint.h>

// HAN: S=256 sentences x W=64 words, E=256, HW=HS=256, C=10
#define SN 256
#define WN 64
#define EN 256
#define HWD 256
#define G3 768

typedef unsigned long long ull;

// ---------------- static device scratch ----------------
__device__ float g_xg[2][WN][SN][G3];      // word input gates, time-major
__device__ float g_wordout[SN][WN][512];   // word BiGRU outputs (F 0..255, B 256..511)
__device__ float g_sent[SN][512];          // sentence vectors
__device__ float g_sxg[2][SN][G3];         // sentence input gates
__device__ float g_sentout[SN][512];       // sentence BiGRU outputs
__device__ float g_hbuf[2][2][SN][HWD];    // word rec h exchange [parity][dir][s][u]
__device__ float g_shbuf[2][2][HWD];       // sent rec h exchange [parity][dir][u]
__device__ unsigned g_bars[32];            // barrier counters

// ---------------- helpers ----------------
__device__ __forceinline__ void fma2(ull& d, ull a, ull b) {
    asm("fma.rn.f32x2 %0, %1, %2, %0;" : "+l"(d) : "l"(a), "l"(b));
}
__device__ __forceinline__ float2 asf2(ull v) {
    float2 r; asm("mov.b64 {%0, %1}, %2;" : "=f"(r.x), "=f"(r.y) : "l"(v)); return r;
}
__device__ __forceinline__ ull mkull(float x, float y) {
    ull v; asm("mov.b64 %0, {%1, %2};" : "=l"(v) : "f"(x), "f"(y)); return v;
}
__device__ __forceinline__ float sigf(float x) {
    return __fdividef(1.0f, 1.0f + __expf(-x));
}
__device__ __forceinline__ float tanh_fast(float x) {
    float e = __expf(-2.0f * x);
    return (1.0f - e) * __fdividef(1.0f, 1.0f + e);
}
__device__ __forceinline__ void bar_arrive(unsigned* p) {
    asm volatile("red.release.gpu.add.u32 [%0], %1;" :: "l"(p), "r"(1u) : "memory");
}
__device__ __forceinline__ unsigned bar_poll(const unsigned* p) {
    unsigned v;
    asm volatile("ld.acquire.gpu.u32 %0, [%1];" : "=r"(v) : "l"(p) : "memory");
    return v;
}

__global__ void k_zero_bars() {
    if (threadIdx.x < 32) g_bars[threadIdx.x] = 0u;
}

// ---------------- kernel 1: word input gates (gathered SGEMM, f32x2) ----------------
// grid (24, 256): 24 col tiles of 64 (F 0..767, B 768..1535), one sentence per blockIdx.y
__global__ void __launch_bounds__(256) k_word_gates(
    const int* __restrict__ toks, const float* __restrict__ emb,
    const float* __restrict__ WihF, const float* __restrict__ WihB,
    const float* __restrict__ bihF, const float* __restrict__ bihB)
{
    __shared__ float As[64][36];   // [row][k0..31 + pad]
    __shared__ float Bs[64][36];
    __shared__ int stok[64];
    const int s   = blockIdx.y;
    const int c0  = blockIdx.x * 64;
    const int dir = (c0 >= G3) ? 1 : 0;
    const int gc0 = c0 - dir * G3;
    const float* __restrict__ Wih = dir ? WihB : WihF;
    const float* __restrict__ bih = dir ? bihB : bihF;
    const int tid = threadIdx.x;
    if (tid < 64) stok[tid] = toks[s * WN + tid];
    __syncthreads();
    const int tx = tid & 15, ty = tid >> 4;
    const int lr = tid >> 3, lk = (tid & 7) << 2;
    ull acc2[4][4];
#pragma unroll
    for (int i = 0; i < 4; i++)
#pragma unroll
        for (int j = 0; j < 4; j++) acc2[i][j] = 0ull;

    for (int k0 = 0; k0 < EN; k0 += 32) {
#pragma unroll
        for (int p = 0; p < 2; p++) {
            const int r = p * 32 + lr;
            *(float4*)&As[r][lk] = *(const float4*)&emb[(size_t)stok[r] * EN + k0 + lk];
            *(float4*)&Bs[r][lk] = *(const float4*)&Wih[(size_t)(gc0 + r) * EN + k0 + lk];
        }
        __syncthreads();
#pragma unroll
        for (int k = 0; k < 32; k += 4) {
            ulonglong2 a_[4], b_[4];
#pragma unroll
            for (int i = 0; i < 4; i++) a_[i] = *(const ulonglong2*)&As[ty * 4 + i][k];
#pragma unroll
            for (int j = 0; j < 4; j++) b_[j] = *(const ulonglong2*)&Bs[tx + 16 * j][k];
#pragma unroll
            for (int i = 0; i < 4; i++)
#pragma unroll
                for (int j = 0; j < 4; j++) {
                    fma2(acc2[i][j], a_[i].x, b_[j].x);
                    fma2(acc2[i][j], a_[i].y, b_[j].y);
                }
        }
        __syncthreads();
    }
#pragma unroll
    for (int j = 0; j < 4; j++) {
        const int cgl = gc0 + tx + 16 * j;
        const float bj = bih[cgl];
#pragma unroll
        for (int i = 0; i < 4; i++) {
            float2 f = asf2(acc2[i][j]);
            g_xg[dir][ty * 4 + i][s][cgl] = f.x + f.y + bj;
        }
    }
}

// ---------------- kernel 2: word recurrence (persistent, f32x2, K quartered, 512 thr) -------
// grid 128 = dir(2) x sent-tile(8 x 32 sents) x unit-tile(8 x 32 units), 512 threads
// thread map: u = tid&31 (unit), sq = (tid>>5)&3 (8-sent quad), kq = tid>>7 (K quarter)
__global__ void __launch_bounds__(512) k_word_rec(
    const float* __restrict__ WhhF, const float* __restrict__ WhhB,
    const float* __restrict__ bhhF, const float* __restrict__ bhhB)
{
    extern __shared__ float sm[];
    float* ws  = sm;                 // [4 kq][32 u][196]  (row = 3*64 gate-kquarter + pad4)
    float* hs  = ws + 4 * 32 * 196;  // [32 sents][256]
    float* cb  = hs + 32 * 256;      // [3][128][25] kq 1..3 partials
    float* sbh = cb + 3 * 128 * 25;  // [96]
    const int blk = blockIdx.x;
    const int dir = blk >> 6;
    const int st  = (blk >> 3) & 7;
    const int ut  = blk & 7;
    const int u0  = ut * 32;
    const int grp = dir * 8 + st;
    const float* __restrict__ Whh = dir ? WhhB : WhhF;
    const float* __restrict__ bhh = dir ? bhhB : bhhF;
    const int tid = threadIdx.x;
    const int u  = tid & 31;
    const int sq = (tid >> 5) & 3;
    const int kq = tid >> 7;

    // weights: ws[(kq*32+uu)*196 + g*64 + kk] = Whh[(g*256+u0+uu)*256 + kq*64 + kk]
    for (int idx = tid * 4; idx < 4 * 32 * 192; idx += 2048) {
        const int khq = idx / 6144;
        const int r2  = idx % 6144;
        const int uu  = r2 / 192;
        const int rem = r2 % 192;
        *(float4*)&ws[(khq * 32 + uu) * 196 + rem] =
            *(const float4*)&Whh[(size_t)((rem >> 6) * 256 + u0 + uu) * 256 + khq * 64 + (rem & 63)];
    }
    if (tid < 96) sbh[tid] = bhh[(tid >> 5) * 256 + u0 + (tid & 31)];
    for (int i = tid; i < 32 * 256; i += 512) hs[i] = 0.0f;
    __syncthreads();

    const float* wku = &ws[(kq * 32 + u) * 196];
    const float bh_r = sbh[u], bh_z = sbh[32 + u], bh_n = sbh[64 + u];
    const int uc = u0 + u;
    const int kb = kq * 64;

    for (int t = 0; t < 64; t++) {
        const int tt = dir ? (63 - t) : t;
        float xr[8], xz[8], xn[8];
        if (kq == 0) {
#pragma unroll
            for (int j = 0; j < 8; j++) {
                const int s = st * 32 + sq * 8 + j;
                xr[j] = g_xg[dir][tt][s][uc];
                xz[j] = g_xg[dir][tt][s][256 + uc];
                xn[j] = g_xg[dir][tt][s][512 + uc];
            }
        }
        ull acc[3][8];
#pragma unroll
        for (int g = 0; g < 3; g++)
#pragma unroll
            for (int j = 0; j < 8; j++) acc[g][j] = 0ull;

#pragma unroll 4
        for (int kk = 0; kk < 64; kk += 4) {
            ulonglong2 w0 = *(const ulonglong2*)&wku[kk];
            ulonglong2 w1 = *(const ulonglong2*)&wku[64 + kk];
            ulonglong2 w2 = *(const ulonglong2*)&wku[128 + kk];
#pragma unroll
            for (int j = 0; j < 8; j++) {
                ulonglong2 h2 = *(const ulonglong2*)&hs[(sq * 8 + j) * 256 + kb + kk];
                fma2(acc[0][j], w0.x, h2.x); fma2(acc[0][j], w0.y, h2.y);
                fma2(acc[1][j], w1.x, h2.x); fma2(acc[1][j], w1.y, h2.y);
                fma2(acc[2][j], w2.x, h2.x); fma2(acc[2][j], w2.y, h2.y);
            }
        }
        float p[24];
#pragma unroll
        for (int g = 0; g < 3; g++)
#pragma unroll
            for (int j = 0; j < 8; j++) {
                float2 f = asf2(acc[g][j]);
                p[g * 8 + j] = f.x + f.y;
            }
        if (kq) {
            float* row = &cb[(kq - 1) * 3200 + (sq * 32 + u) * 25];
#pragma unroll
            for (int i = 0; i < 24; i++) row[i] = p[i];
        }
        __syncthreads();
        const int par = (t + 1) & 1;
        if (kq == 0) {
#pragma unroll
            for (int q = 0; q < 3; q++) {
                const float* row = &cb[q * 3200 + (sq * 32 + u) * 25];
#pragma unroll
                for (int i = 0; i < 24; i++) p[i] += row[i];
            }
#pragma unroll
            for (int j = 0; j < 8; j++) {
                const int sl = sq * 8 + j;
                const int s  = st * 32 + sl;
                const float r = sigf(xr[j] + p[j] + bh_r);
                const float z = sigf(xz[j] + p[8 + j] + bh_z);
                const float n = tanh_fast(xn[j] + r * (p[16 + j] + bh_n));
                const float hold = hs[sl * 256 + uc];
                const float hnew = (1.0f - z) * n + z * hold;
                __stcg(&g_hbuf[par][dir][s][uc], hnew);
                g_wordout[s][tt][dir * 256 + uc] = hnew;
            }
        }
        __syncthreads();
        if (tid == 0) {
            bar_arrive(&g_bars[grp]);
            const unsigned tgt = 8u * (unsigned)(t + 1);
            while (bar_poll(&g_bars[grp]) < tgt) { }
        }
        __syncthreads();
        if (t < 63) {
            const float* src = &g_hbuf[par][dir][st * 32][0];
            for (int i = tid * 4; i < 32 * 256; i += 2048)
                *(float4*)&hs[i] = __ldcg((const float4*)(src + i));
            __syncthreads();
        }
    }
}

// ---------------- kernel 3: word attention pool -> sentence vectors ----------------
__global__ void __launch_bounds__(256) k_word_attn(
    const float* __restrict__ attw, const float* __restrict__ attb)
{
    __shared__ float sc[64];
    const int s = blockIdx.x;
    const int tid = threadIdx.x, wp = tid >> 5, ln = tid & 31;
    const float bb = attb[0];
    for (int w = wp; w < 64; w += 8) {
        const float* op = &g_wordout[s][w][0];
        float d = 0.0f;
#pragma unroll
        for (int i = 0; i < 4; i++) {
            float4 o = *(const float4*)&op[ln * 16 + i * 4];
            float4 a = *(const float4*)&attw[ln * 16 + i * 4];
            d += o.x * a.x + o.y * a.y + o.z * a.z + o.w * a.w;
        }
#pragma unroll
        for (int off = 16; off > 0; off >>= 1) d += __shfl_xor_sync(0xffffffffu, d, off);
        if (ln == 0) sc[w] = tanhf(d + bb);
    }
    __syncthreads();
    if (tid < 32) {
        float a0 = sc[tid], a1 = sc[tid + 32];
        float m = fmaxf(a0, a1);
#pragma unroll
        for (int off = 16; off > 0; off >>= 1) m = fmaxf(m, __shfl_xor_sync(0xffffffffu, m, off));
        float e0 = expf(a0 - m), e1 = expf(a1 - m);
        float ssum = e0 + e1;
#pragma unroll
        for (int off = 16; off > 0; off >>= 1) ssum += __shfl_xor_sync(0xffffffffu, ssum, off);
        sc[tid] = e0 / ssum; sc[tid + 32] = e1 / ssum;
    }
    __syncthreads();
    float acc0 = 0.0f, acc1 = 0.0f;
    for (int w = 0; w < 64; w++) {
        const float a = sc[w];
        acc0 += a * g_wordout[s][w][tid];
        acc1 += a * g_wordout[s][w][tid + 256];
    }
    g_sent[s][tid] = acc0;
    g_sent[s][tid + 256] = acc1;
}

// ---------------- kernel 4: sentence input gates (SGEMM K=512, f32x2) ----------------
// grid (24, 4)
__global__ void __launch_bounds__(256) k_sent_gates(
    const float* __restrict__ WihF, const float* __restrict__ WihB,
    const float* __restrict__ bihF, const float* __restrict__ bihB)
{
    __shared__ float As[64][36];
    __shared__ float Bs[64][36];
    const int s0  = blockIdx.y * 64;
    const int c0  = blockIdx.x * 64;
    const int dir = (c0 >= G3) ? 1 : 0;
    const int gc0 = c0 - dir * G3;
    const float* __restrict__ Wih = dir ? WihB : WihF;
    const float* __restrict__ bih = dir ? bihB : bihF;
    const int tid = threadIdx.x;
    const int tx = tid & 15, ty = tid >> 4;
    const int lr = tid >> 3, lk = (tid & 7) << 2;
    ull acc2[4][4];
#pragma unroll
    for (int i = 0; i < 4; i++)
#pragma unroll
        for (int j = 0; j < 4; j++) acc2[i][j] = 0ull;

    for (int k0 = 0; k0 < 512; k0 += 32) {
#pragma unroll
        for (int p = 0; p < 2; p++) {
            const int r = p * 32 + lr;
            *(float4*)&As[r][lk] = *(const float4*)&g_sent[s0 + r][k0 + lk];
            *(float4*)&Bs[r][lk] = *(const float4*)&Wih[(size_t)(gc0 + r) * 512 + k0 + lk];
        }
        __syncthreads();
#pragma unroll
        for (int k = 0; k < 32; k += 4) {
            ulonglong2 a_[4], b_[4];
#pragma unroll
            for (int i = 0; i < 4; i++) a_[i] = *(const ulonglong2*)&As[ty * 4 + i][k];
#pragma unroll
            for (int j = 0; j < 4; j++) b_[j] = *(const ulonglong2*)&Bs[tx + 16 * j][k];
#pragma unroll
            for (int i = 0; i < 4; i++)
#pragma unroll
                for (int j = 0; j < 4; j++) {
                    fma2(acc2[i][j], a_[i].x, b_[j].x);
                    fma2(acc2[i][j], a_[i].y, b_[j].y);
                }
        }
        __syncthreads();
    }
#pragma unroll
    for (int j = 0; j < 4; j++) {
        const int cgl = gc0 + tx + 16 * j;
        const float bj = bih[cgl];
#pragma unroll
        for (int i = 0; i < 4; i++) {
            float2 f = asf2(acc2[i][j]);
            g_sxg[dir][s0 + ty * 4 + i][cgl] = f.x + f.y + bj;
        }
    }
}

// ---------------- kernel 5: sentence recurrence (weights in registers, 8-CTA cluster) -------
// grid 16 = dir(2) x unit-tile(8 x 32 units) = 2 clusters of 8, 384 threads
// thread map: warp w (0..11), lane l: row r = w*8 + (l>>2) (0..95), K-quarter q = l&3
__global__ void __launch_bounds__(384) __cluster_dims__(8, 1, 1) k_sent_rec(
    const float* __restrict__ WhhF, const float* __restrict__ WhhB,
    const float* __restrict__ bhhF, const float* __restrict__ bhhB)
{
    __shared__ float hsm[4 * 68];   // h, quarter-padded: u -> hsm[(u>>6)*68 + (u&63)]
    __shared__ float gv[96];        // gate values: r = gate*32 + ulocal
    const int dir = blockIdx.x >> 3;
    const int ut  = blockIdx.x & 7;
    const int u0  = ut * 32;
    const float* __restrict__ Whh = dir ? WhhB : WhhF;
    const float* __restrict__ bhh = dir ? bhhB : bhhF;
    const int tid = threadIdx.x;
    const int l = tid & 31;
    const int r = (tid >> 5) * 8 + (l >> 2);
    const int q = l & 3;
    const int row = (r >> 5) * 256 + u0 + (r & 31);

    // load this thread's 64 weights (its K-quarter of the row) into registers
    ull wreg[32];
    {
        const float4* wsrc = (const float4*)&Whh[(size_t)row * 256 + q * 64];
#pragma unroll
        for (int i = 0; i < 16; i++) {
            float4 v = wsrc[i];
            wreg[2 * i]     = mkull(v.x, v.y);
            wreg[2 * i + 1] = mkull(v.z, v.w);
        }
    }
    const float bh = bhh[row];
    for (int k = tid; k < 4 * 68; k += 384) hsm[k] = 0.0f;
    __syncthreads();
    asm volatile("barrier.cluster.arrive.aligned;" ::: "memory");
    asm volatile("barrier.cluster.wait.aligned;" ::: "memory");

    for (int t = 0; t < 256; t++) {
        const int tt = dir ? (255 - t) : t;
        float xr = 0.0f, xz = 0.0f, xn = 0.0f;
        if (tid < 32) {
            const int u = u0 + tid;
            xr = g_sxg[dir][tt][u];
            xz = g_sxg[dir][tt][256 + u];
            xn = g_sxg[dir][tt][512 + u];
        }
        ull acc2 = 0ull;
#pragma unroll
        for (int i = 0; i < 16; i++) {
            ulonglong2 h2 = *(const ulonglong2*)&hsm[q * 68 + i * 4];
            fma2(acc2, h2.x, wreg[2 * i]);
            fma2(acc2, h2.y, wreg[2 * i + 1]);
        }
        float2 fa = asf2(acc2);
        float s = fa.x + fa.y;
        s += __shfl_xor_sync(0xffffffffu, s, 1);
        s += __shfl_xor_sync(0xffffffffu, s, 2);
        if (q == 0) gv[r] = s + bh;
        __syncthreads();
        const int par = (t + 1) & 1;
        if (tid < 32) {
            const int u = u0 + tid;
            const float hold = hsm[(u >> 6) * 68 + (u & 63)];
            const float rr = sigf(xr + gv[tid]);
            const float zz = sigf(xz + gv[32 + tid]);
            const float nn = tanh_fast(xn + rr * gv[64 + tid]);
            const float hnew = (1.0f - zz) * nn + zz * hold;
            __stcg(&g_shbuf[par][dir][u], hnew);
            g_sentout[tt][dir * 256 + u] = hnew;
        }
        // cluster barrier: releases the stcg above, acquires peers' h for the reload below
        asm volatile("barrier.cluster.arrive.aligned;" ::: "memory");
        asm volatile("barrier.cluster.wait.aligned;" ::: "memory");
        if (t < 255) {
            if (tid < 256)
                hsm[(tid >> 6) * 68 + (tid & 63)] = __ldcg(&g_shbuf[par][dir][tid]);
            __syncthreads();
        }
    }
}

// ---------------- kernel 6: sentence attention + classifier + softmax ----------------
__global__ void __launch_bounds__(256) k_doc(
    const float* __restrict__ attw, const float* __restrict__ attb,
    const float* __restrict__ clsW, const float* __restrict__ clsB,
    float* __restrict__ out)
{
    __shared__ float sc[256];
    __shared__ float red[8];
    __shared__ float docv[512];
    __shared__ float lg[10];
    const int tid = threadIdx.x, wp = tid >> 5, ln = tid & 31;
    const float bb = attb[0];
    for (int s = wp; s < 256; s += 8) {
        const float* op = &g_sentout[s][0];
        float d = 0.0f;
#pragma unroll
        for (int i = 0; i < 4; i++) {
            float4 o = *(const float4*)&op[ln * 16 + i * 4];
            float4 a = *(const float4*)&attw[ln * 16 + i * 4];
            d += o.x * a.x + o.y * a.y + o.z * a.z + o.w * a.w;
        }
#pragma unroll
        for (int off = 16; off > 0; off >>= 1) d += __shfl_xor_sync(0xffffffffu, d, off);
        if (ln == 0) sc[s] = tanhf(d + bb);
    }
    __syncthreads();
    float v = sc[tid];
    float m = v;
#pragma unroll
    for (int off = 16; off > 0; off >>= 1) m = fmaxf(m, __shfl_xor_sync(0xffffffffu, m, off));
    if (ln == 0) red[wp] = m;
    __syncthreads();
    if (tid < 8) {
        float mm = red[tid];
#pragma unroll
        for (int off = 4; off > 0; off >>= 1) mm = fmaxf(mm, __shfl_xor_sync(0xffu, mm, off));
        red[tid] = mm;
    }
    __syncthreads();
    const float gm = red[0];
    float e = expf(v - gm);
    float ssum = e;
#pragma unroll
    for (int off = 16; off > 0; off >>= 1) ssum += __shfl_xor_sync(0xffffffffu, ssum, off);
    __syncthreads();
    if (ln == 0) red[wp] = ssum;
    __syncthreads();
    if (tid < 8) {
        float s2 = red[tid];
#pragma unroll
        for (int off = 4; off > 0; off >>= 1) s2 += __shfl_xor_sync(0xffu, s2, off);
        red[tid] = s2;
    }
    __syncthreads();
    const float tot = red[0];
    sc[tid] = e / tot;
    __syncthreads();
    float a0 = 0.0f, a1 = 0.0f;
    for (int s = 0; s < 256; s++) {
        const float a = sc[s];
        a0 += a * g_sentout[s][tid];
        a1 += a * g_sentout[s][tid + 256];
    }
    docv[tid] = a0; docv[tid + 256] = a1;
    __syncthreads();
    for (int o = wp; o < 10; o += 8) {
        const float* wr = &clsW[o * 512];
        float d = 0.0f;
#pragma unroll
        for (int i = 0; i < 4; i++) {
            float4 x = *(const float4*)&docv[ln * 16 + i * 4];
            float4 w = *(const float4*)&wr[ln * 16 + i * 4];
            d += x.x * w.x + x.y * w.y + x.z * w.z + x.w * w.w;
        }
#pragma unroll
        for (int off = 16; off > 0; off >>= 1) d += __shfl_xor_sync(0xffffffffu, d, off);
        if (ln == 0) lg[o] = d + clsB[o];
    }
    __syncthreads();
    if (tid == 0) {
        float mm = lg[0];
        for (int i = 1; i < 10; i++) mm = fmaxf(mm, lg[i]);
        float s2 = 0.0f;
        float ee[10];
        for (int i = 0; i < 10; i++) { ee[i] = expf(lg[i] - mm); s2 += ee[i]; }
        for (int i = 0; i < 10; i++) out[i] = ee[i] / s2;
    }
}

// ---------------- launch ----------------
extern "C" void kernel_launch(void* const* d_in, const int* in_sizes, int n_in,
                              void* d_out, int out_size) {
    const int*   toks  = (const int*)d_in[0];
    const float* emb   = (const float*)d_in[1];
    const float* wWihF = (const float*)d_in[2];
    const float* wWhhF = (const float*)d_in[3];
    const float* wBihF = (const float*)d_in[4];
    const float* wBhhF = (const float*)d_in[5];
    const float* wWihB = (const float*)d_in[6];
    const float* wWhhB = (const float*)d_in[7];
    const float* wBihB = (const float*)d_in[8];
    const float* wBhhB = (const float*)d_in[9];
    const float* sWihF = (const float*)d_in[10];
    const float* sWhhF = (const float*)d_in[11];
    const float* sBihF = (const float*)d_in[12];
    const float* sBhhF = (const float*)d_in[13];
    const float* sWihB = (const float*)d_in[14];
    const float* sWhhB = (const float*)d_in[15];
    const float* sBihB = (const float*)d_in[16];
    const float* sBhhB = (const float*)d_in[17];
    const float* wAttW = (const float*)d_in[18];
    const float* wAttB = (const float*)d_in[19];
    const float* sAttW = (const float*)d_in[20];
    const float* sAttB = (const float*)d_in[21];
    const float* clsW  = (const float*)d_in[22];
    const float* clsB  = (const float*)d_in[23];
    float* out = (float*)d_out;

    const int WREC_SMEM = (4 * 32 * 196 + 32 * 256 + 3 * 128 * 25 + 96) * 4;  // 171904
    cudaFuncSetAttribute(k_word_rec, cudaFuncAttributeMaxDynamicSharedMemorySize, WREC_SMEM);

    k_zero_bars<<<1, 32>>>();
    k_zero_bars<<<1, 32>>>();   // dummy: keeps k_word_rec in the ncu-captured launch slot
    dim3 g1(24, 256);
    k_word_gates<<<g1, 256>>>(toks, emb, wWihF, wWihB, wBihF, wBihB);
    k_word_rec<<<128, 512, WREC_SMEM>>>(wWhhF, wWhhB, wBhhF, wBhhB);
    k_word_attn<<<256, 256>>>(wAttW, wAttB);
    dim3 g2(24, 4);
    k_sent_gates<<<g2, 256>>>(sWihF, sWihB, sBihF, sBihB);
    k_sent_rec<<<16, 384>>>(sWhhF, sWhhB, sBhhF, sBhhB);
    k_doc<<<1, 256>>>(sAttW, sAttB, clsW, clsB, out);
}

// round 9
// speedup vs baseline: 1.4354x; 1.0218x over previous
#include <cuda_runtime.h>
#include <math.h>
#include <stdint.h>

// HAN: S=256 sentences x W=64 words, E=256, HW=HS=256, C=10
#define SN 256
#define WN 64
#define EN 256
#define HWD 256
#define G3 768

typedef unsigned long long ull;

// ---------------- static device scratch ----------------
__device__ float g_xg[2][WN][SN][G3];      // word input gates, time-major
__device__ float g_wordout[SN][WN][512];   // word BiGRU outputs (F 0..255, B 256..511)
__device__ float g_sent[SN][512];          // sentence vectors
__device__ float g_sxg[2][SN][G3];         // sentence input gates
__device__ float g_sentout[SN][512];       // sentence BiGRU outputs
__device__ float g_hbuf[2][2][SN][HWD];    // word rec h exchange [parity][dir][s][u]
__device__ float g_shbuf[2][2][HWD];       // sent rec h exchange [parity][dir][u]
__device__ unsigned g_bars[32];            // barrier counters

// ---------------- helpers ----------------
__device__ __forceinline__ void fma2(ull& d, ull a, ull b) {
    asm("fma.rn.f32x2 %0, %1, %2, %0;" : "+l"(d) : "l"(a), "l"(b));
}
__device__ __forceinline__ float2 asf2(ull v) {
    float2 r; asm("mov.b64 {%0, %1}, %2;" : "=f"(r.x), "=f"(r.y) : "l"(v)); return r;
}
__device__ __forceinline__ ull mkull(float x, float y) {
    ull v; asm("mov.b64 %0, {%1, %2};" : "=l"(v) : "f"(x), "f"(y)); return v;
}
__device__ __forceinline__ float sigf(float x) {
    return __fdividef(1.0f, 1.0f + __expf(-x));
}
__device__ __forceinline__ float tanh_fast(float x) {
    float e = __expf(-2.0f * x);
    return (1.0f - e) * __fdividef(1.0f, 1.0f + e);
}
__device__ __forceinline__ void bar_arrive(unsigned* p) {
    asm volatile("red.release.gpu.add.u32 [%0], %1;" :: "l"(p), "r"(1u) : "memory");
}
__device__ __forceinline__ unsigned bar_poll(const unsigned* p) {
    unsigned v;
    asm volatile("ld.acquire.gpu.u32 %0, [%1];" : "=r"(v) : "l"(p) : "memory");
    return v;
}

__global__ void k_zero_bars() {
    if (threadIdx.x < 32) g_bars[threadIdx.x] = 0u;
}

// ---------------- kernel 1: word input gates (gathered SGEMM, f32x2) ----------------
// grid (24, 256): 24 col tiles of 64 (F 0..767, B 768..1535), one sentence per blockIdx.y
__global__ void __launch_bounds__(256) k_word_gates(
    const int* __restrict__ toks, const float* __restrict__ emb,
    const float* __restrict__ WihF, const float* __restrict__ WihB,
    const float* __restrict__ bihF, const float* __restrict__ bihB)
{
    __shared__ float As[64][36];   // [row][k0..31 + pad]
    __shared__ float Bs[64][36];
    __shared__ int stok[64];
    const int s   = blockIdx.y;
    const int c0  = blockIdx.x * 64;
    const int dir = (c0 >= G3) ? 1 : 0;
    const int gc0 = c0 - dir * G3;
    const float* __restrict__ Wih = dir ? WihB : WihF;
    const float* __restrict__ bih = dir ? bihB : bihF;
    const int tid = threadIdx.x;
    if (tid < 64) stok[tid] = toks[s * WN + tid];
    __syncthreads();
    const int tx = tid & 15, ty = tid >> 4;
    const int lr = tid >> 3, lk = (tid & 7) << 2;
    ull acc2[4][4];
#pragma unroll
    for (int i = 0; i < 4; i++)
#pragma unroll
        for (int j = 0; j < 4; j++) acc2[i][j] = 0ull;

    for (int k0 = 0; k0 < EN; k0 += 32) {
#pragma unroll
        for (int p = 0; p < 2; p++) {
            const int r = p * 32 + lr;
            *(float4*)&As[r][lk] = *(const float4*)&emb[(size_t)stok[r] * EN + k0 + lk];
            *(float4*)&Bs[r][lk] = *(const float4*)&Wih[(size_t)(gc0 + r) * EN + k0 + lk];
        }
        __syncthreads();
#pragma unroll
        for (int k = 0; k < 32; k += 4) {
            ulonglong2 a_[4], b_[4];
#pragma unroll
            for (int i = 0; i < 4; i++) a_[i] = *(const ulonglong2*)&As[ty * 4 + i][k];
#pragma unroll
            for (int j = 0; j < 4; j++) b_[j] = *(const ulonglong2*)&Bs[tx + 16 * j][k];
#pragma unroll
            for (int i = 0; i < 4; i++)
#pragma unroll
                for (int j = 0; j < 4; j++) {
                    fma2(acc2[i][j], a_[i].x, b_[j].x);
                    fma2(acc2[i][j], a_[i].y, b_[j].y);
                }
        }
        __syncthreads();
    }
#pragma unroll
    for (int j = 0; j < 4; j++) {
        const int cgl = gc0 + tx + 16 * j;
        const float bj = bih[cgl];
#pragma unroll
        for (int i = 0; i < 4; i++) {
            float2 f = asf2(acc2[i][j]);
            g_xg[dir][ty * 4 + i][s][cgl] = f.x + f.y + bj;
        }
    }
}

// ---------------- kernel 2: word recurrence (persistent, f32x2, K halved, 256 thr) ----------
// grid 128 = dir(2) x sent-tile(8 x 32 sents) x unit-tile(8 x 32 units), 256 threads
// thread map: u = tid&31 (unit), sq = (tid>>5)&3 (8-sent quad), kh = tid>>7 (K half)
// GRU epilogue split: each (u,sq,kh) thread finalizes sents j = kh*4 .. kh*4+3
__global__ void __launch_bounds__(256) k_word_rec(
    const float* __restrict__ WhhF, const float* __restrict__ WhhB,
    const float* __restrict__ bhhF, const float* __restrict__ bhhB)
{
    extern __shared__ float sm[];
    float* ws  = sm;                 // [2 kh][32 u][388]  (row = 3*128 gate-khalf + pad4)
    float* hs  = ws + 2 * 32 * 388;  // [32 sents][256]
    float* cb  = hs + 32 * 256;      // [2 kh][128][25] partials
    float* sbh = cb + 2 * 128 * 25;  // [96]
    const int blk = blockIdx.x;
    const int dir = blk >> 6;
    const int st  = (blk >> 3) & 7;
    const int ut  = blk & 7;
    const int u0  = ut * 32;
    const int grp = dir * 8 + st;
    const float* __restrict__ Whh = dir ? WhhB : WhhF;
    const float* __restrict__ bhh = dir ? bhhB : bhhF;
    const int tid = threadIdx.x;
    const int u  = tid & 31;
    const int sq = (tid >> 5) & 3;
    const int kh = tid >> 7;

    // weights: ws[(kh*32+uu)*388 + g*128 + kk] = Whh[(g*256+u0+uu)*256 + kh*128 + kk]
    for (int idx = tid * 4; idx < 2 * 32 * 384; idx += 1024) {
        const int khh = idx / 12288;
        const int r2  = idx % 12288;
        const int uu  = r2 / 384;
        const int rem = r2 % 384;
        const int g = rem >> 7, kk = rem & 127;
        *(float4*)&ws[(khh * 32 + uu) * 388 + rem] =
            *(const float4*)&Whh[(size_t)(g * 256 + u0 + uu) * 256 + khh * 128 + kk];
    }
    if (tid < 96) sbh[tid] = bhh[(tid >> 5) * 256 + u0 + (tid & 31)];
    for (int i = tid; i < 32 * 256; i += 256) hs[i] = 0.0f;
    __syncthreads();

    const float* wku = &ws[(kh * 32 + u) * 388];
    const float bh_r = sbh[u], bh_z = sbh[32 + u], bh_n = sbh[64 + u];
    const int uc = u0 + u;
    const int kb = kh * 128;
    const int jb = kh * 4;           // this thread's 4 epilogue sents

    for (int t = 0; t < 64; t++) {
        const int tt = dir ? (63 - t) : t;
        // prefetch x-gates for this thread's 4 assigned sents
        float xr[4], xz[4], xn[4];
#pragma unroll
        for (int jj = 0; jj < 4; jj++) {
            const int s = st * 32 + sq * 8 + jb + jj;
            xr[jj] = g_xg[dir][tt][s][uc];
            xz[jj] = g_xg[dir][tt][s][256 + uc];
            xn[jj] = g_xg[dir][tt][s][512 + uc];
        }
        ull acc[3][8];
#pragma unroll
        for (int g = 0; g < 3; g++)
#pragma unroll
            for (int j = 0; j < 8; j++) acc[g][j] = 0ull;

#pragma unroll 4
        for (int kk = 0; kk < 128; kk += 4) {
            ulonglong2 w0 = *(const ulonglong2*)&wku[kk];
            ulonglong2 w1 = *(const ulonglong2*)&wku[128 + kk];
            ulonglong2 w2 = *(const ulonglong2*)&wku[256 + kk];
#pragma unroll
            for (int j = 0; j < 8; j++) {
                ulonglong2 h2 = *(const ulonglong2*)&hs[(sq * 8 + j) * 256 + kb + kk];
                fma2(acc[0][j], w0.x, h2.x); fma2(acc[0][j], w0.y, h2.y);
                fma2(acc[1][j], w1.x, h2.x); fma2(acc[1][j], w1.y, h2.y);
                fma2(acc[2][j], w2.x, h2.x); fma2(acc[2][j], w2.y, h2.y);
            }
        }
        // every thread stores its 24 partials
        {
            float* row = &cb[kh * 3200 + (sq * 32 + u) * 25];
#pragma unroll
            for (int g = 0; g < 3; g++)
#pragma unroll
                for (int j = 0; j < 8; j++) {
                    float2 f = asf2(acc[g][j]);
                    row[g * 8 + j] = f.x + f.y;
                }
        }
        __syncthreads();
        const int par = (t + 1) & 1;
        // each thread finalizes 4 sents (jb..jb+3) of its (sq,u)
        {
            const float* r0 = &cb[(sq * 32 + u) * 25];
            const float* r1 = &cb[3200 + (sq * 32 + u) * 25];
#pragma unroll
            for (int jj = 0; jj < 4; jj++) {
                const int j  = jb + jj;
                const int sl = sq * 8 + j;
                const int s  = st * 32 + sl;
                const float pr = r0[j]      + r1[j];
                const float pz = r0[8 + j]  + r1[8 + j];
                const float pn = r0[16 + j] + r1[16 + j];
                const float r = sigf(xr[jj] + pr + bh_r);
                const float z = sigf(xz[jj] + pz + bh_z);
                const float n = tanh_fast(xn[jj] + r * (pn + bh_n));
                const float hold = hs[sl * 256 + uc];
                const float hnew = (1.0f - z) * n + z * hold;
                __stcg(&g_hbuf[par][dir][s][uc], hnew);
                g_wordout[s][tt][dir * 256 + uc] = hnew;
            }
        }
        __syncthreads();
        if (tid == 0) {
            bar_arrive(&g_bars[grp]);
            const unsigned tgt = 8u * (unsigned)(t + 1);
            while (bar_poll(&g_bars[grp]) < tgt) { }
        }
        __syncthreads();
        if (t < 63) {
            const float* src = &g_hbuf[par][dir][st * 32][0];
            for (int i = tid * 4; i < 32 * 256; i += 1024)
                *(float4*)&hs[i] = __ldcg((const float4*)(src + i));
            __syncthreads();
        }
    }
}

// ---------------- kernel 3: word attention pool -> sentence vectors ----------------
__global__ void __launch_bounds__(256) k_word_attn(
    const float* __restrict__ attw, const float* __restrict__ attb)
{
    __shared__ float sc[64];
    const int s = blockIdx.x;
    const int tid = threadIdx.x, wp = tid >> 5, ln = tid & 31;
    const float bb = attb[0];
    for (int w = wp; w < 64; w += 8) {
        const float* op = &g_wordout[s][w][0];
        float d = 0.0f;
#pragma unroll
        for (int i = 0; i < 4; i++) {
            float4 o = *(const float4*)&op[ln * 16 + i * 4];
            float4 a = *(const float4*)&attw[ln * 16 + i * 4];
            d += o.x * a.x + o.y * a.y + o.z * a.z + o.w * a.w;
        }
#pragma unroll
        for (int off = 16; off > 0; off >>= 1) d += __shfl_xor_sync(0xffffffffu, d, off);
        if (ln == 0) sc[w] = tanhf(d + bb);
    }
    __syncthreads();
    if (tid < 32) {
        float a0 = sc[tid], a1 = sc[tid + 32];
        float m = fmaxf(a0, a1);
#pragma unroll
        for (int off = 16; off > 0; off >>= 1) m = fmaxf(m, __shfl_xor_sync(0xffffffffu, m, off));
        float e0 = expf(a0 - m), e1 = expf(a1 - m);
        float ssum = e0 + e1;
#pragma unroll
        for (int off = 16; off > 0; off >>= 1) ssum += __shfl_xor_sync(0xffffffffu, ssum, off);
        sc[tid] = e0 / ssum; sc[tid + 32] = e1 / ssum;
    }
    __syncthreads();
    float acc0 = 0.0f, acc1 = 0.0f;
    for (int w = 0; w < 64; w++) {
        const float a = sc[w];
        acc0 += a * g_wordout[s][w][tid];
        acc1 += a * g_wordout[s][w][tid + 256];
    }
    g_sent[s][tid] = acc0;
    g_sent[s][tid + 256] = acc1;
}

// ---------------- kernel 4: sentence input gates (SGEMM K=512, f32x2) ----------------
// grid (24, 4)
__global__ void __launch_bounds__(256) k_sent_gates(
    const float* __restrict__ WihF, const float* __restrict__ WihB,
    const float* __restrict__ bihF, const float* __restrict__ bihB)
{
    __shared__ float As[64][36];
    __shared__ float Bs[64][36];
    const int s0  = blockIdx.y * 64;
    const int c0  = blockIdx.x * 64;
    const int dir = (c0 >= G3) ? 1 : 0;
    const int gc0 = c0 - dir * G3;
    const float* __restrict__ Wih = dir ? WihB : WihF;
    const float* __restrict__ bih = dir ? bihB : bihF;
    const int tid = threadIdx.x;
    const int tx = tid & 15, ty = tid >> 4;
    const int lr = tid >> 3, lk = (tid & 7) << 2;
    ull acc2[4][4];
#pragma unroll
    for (int i = 0; i < 4; i++)
#pragma unroll
        for (int j = 0; j < 4; j++) acc2[i][j] = 0ull;

    for (int k0 = 0; k0 < 512; k0 += 32) {
#pragma unroll
        for (int p = 0; p < 2; p++) {
            const int r = p * 32 + lr;
            *(float4*)&As[r][lk] = *(const float4*)&g_sent[s0 + r][k0 + lk];
            *(float4*)&Bs[r][lk] = *(const float4*)&Wih[(size_t)(gc0 + r) * 512 + k0 + lk];
        }
        __syncthreads();
#pragma unroll
        for (int k = 0; k < 32; k += 4) {
            ulonglong2 a_[4], b_[4];
#pragma unroll
            for (int i = 0; i < 4; i++) a_[i] = *(const ulonglong2*)&As[ty * 4 + i][k];
#pragma unroll
            for (int j = 0; j < 4; j++) b_[j] = *(const ulonglong2*)&Bs[tx + 16 * j][k];
#pragma unroll
            for (int i = 0; i < 4; i++)
#pragma unroll
                for (int j = 0; j < 4; j++) {
                    fma2(acc2[i][j], a_[i].x, b_[j].x);
                    fma2(acc2[i][j], a_[i].y, b_[j].y);
                }
        }
        __syncthreads();
    }
#pragma unroll
    for (int j = 0; j < 4; j++) {
        const int cgl = gc0 + tx + 16 * j;
        const float bj = bih[cgl];
#pragma unroll
        for (int i = 0; i < 4; i++) {
            float2 f = asf2(acc2[i][j]);
            g_sxg[dir][s0 + ty * 4 + i][cgl] = f.x + f.y + bj;
        }
    }
}

// ---------------- kernel 5: sentence recurrence (weights in registers, 8-CTA cluster) -------
// grid 16 = dir(2) x unit-tile(8 x 32 units) = 2 clusters of 8, 384 threads
// thread map: warp w (0..11), lane l: row r = w*8 + (l>>2) (0..95), K-quarter q = l&3
__global__ void __launch_bounds__(384) __cluster_dims__(8, 1, 1) k_sent_rec(
    const float* __restrict__ WhhF, const float* __restrict__ WhhB,
    const float* __restrict__ bhhF, const float* __restrict__ bhhB)
{
    __shared__ float hsm[4 * 68];   // h, quarter-padded: u -> hsm[(u>>6)*68 + (u&63)]
    __shared__ float gv[96];        // gate values: r = gate*32 + ulocal
    const int dir = blockIdx.x >> 3;
    const int ut  = blockIdx.x & 7;
    const int u0  = ut * 32;
    const float* __restrict__ Whh = dir ? WhhB : WhhF;
    const float* __restrict__ bhh = dir ? bhhB : bhhF;
    const int tid = threadIdx.x;
    const int l = tid & 31;
    const int r = (tid >> 5) * 8 + (l >> 2);
    const int q = l & 3;
    const int row = (r >> 5) * 256 + u0 + (r & 31);

    // load this thread's 64 weights (its K-quarter of the row) into registers
    ull wreg[32];
    {
        const float4* wsrc = (const float4*)&Whh[(size_t)row * 256 + q * 64];
#pragma unroll
        for (int i = 0; i < 16; i++) {
            float4 v = wsrc[i];
            wreg[2 * i]     = mkull(v.x, v.y);
            wreg[2 * i + 1] = mkull(v.z, v.w);
        }
    }
    const float bh = bhh[row];
    for (int k = tid; k < 4 * 68; k += 384) hsm[k] = 0.0f;
    __syncthreads();
    asm volatile("barrier.cluster.arrive.aligned;" ::: "memory");
    asm volatile("barrier.cluster.wait.aligned;" ::: "memory");

    for (int t = 0; t < 256; t++) {
        const int tt = dir ? (255 - t) : t;
        float xr = 0.0f, xz = 0.0f, xn = 0.0f;
        if (tid < 32) {
            const int u = u0 + tid;
            xr = g_sxg[dir][tt][u];
            xz = g_sxg[dir][tt][256 + u];
            xn = g_sxg[dir][tt][512 + u];
        }
        ull acc2 = 0ull;
#pragma unroll
        for (int i = 0; i < 16; i++) {
            ulonglong2 h2 = *(const ulonglong2*)&hsm[q * 68 + i * 4];
            fma2(acc2, h2.x, wreg[2 * i]);
            fma2(acc2, h2.y, wreg[2 * i + 1]);
        }
        float2 fa = asf2(acc2);
        float s = fa.x + fa.y;
        s += __shfl_xor_sync(0xffffffffu, s, 1);
        s += __shfl_xor_sync(0xffffffffu, s, 2);
        if (q == 0) gv[r] = s + bh;
        __syncthreads();
        const int par = (t + 1) & 1;
        if (tid < 32) {
            const int u = u0 + tid;
            const float hold = hsm[(u >> 6) * 68 + (u & 63)];
            const float rr = sigf(xr + gv[tid]);
            const float zz = sigf(xz + gv[32 + tid]);
            const float nn = tanh_fast(xn + rr * gv[64 + tid]);
            const float hnew = (1.0f - zz) * nn + zz * hold;
            __stcg(&g_shbuf[par][dir][u], hnew);
            g_sentout[tt][dir * 256 + u] = hnew;
        }
        // cluster barrier: releases the stcg above, acquires peers' h for the reload below
        asm volatile("barrier.cluster.arrive.aligned;" ::: "memory");
        asm volatile("barrier.cluster.wait.aligned;" ::: "memory");
        if (t < 255) {
            if (tid < 256)
                hsm[(tid >> 6) * 68 + (tid & 63)] = __ldcg(&g_shbuf[par][dir][tid]);
            __syncthreads();
        }
    }
}

// ---------------- kernel 6: sentence attention + classifier + softmax ----------------
__global__ void __launch_bounds__(256) k_doc(
    const float* __restrict__ attw, const float* __restrict__ attb,
    const float* __restrict__ clsW, const float* __restrict__ clsB,
    float* __restrict__ out)
{
    __shared__ float sc[256];
    __shared__ float red[8];
    __shared__ float docv[512];
    __shared__ float lg[10];
    const int tid = threadIdx.x, wp = tid >> 5, ln = tid & 31;
    const float bb = attb[0];
    for (int s = wp; s < 256; s += 8) {
        const float* op = &g_sentout[s][0];
        float d = 0.0f;
#pragma unroll
        for (int i = 0; i < 4; i++) {
            float4 o = *(const float4*)&op[ln * 16 + i * 4];
            float4 a = *(const float4*)&attw[ln * 16 + i * 4];
            d += o.x * a.x + o.y * a.y + o.z * a.z + o.w * a.w;
        }
#pragma unroll
        for (int off = 16; off > 0; off >>= 1) d += __shfl_xor_sync(0xffffffffu, d, off);
        if (ln == 0) sc[s] = tanhf(d + bb);
    }
    __syncthreads();
    float v = sc[tid];
    float m = v;
#pragma unroll
    for (int off = 16; off > 0; off >>= 1) m = fmaxf(m, __shfl_xor_sync(0xffffffffu, m, off));
    if (ln == 0) red[wp] = m;
    __syncthreads();
    if (tid < 8) {
        float mm = red[tid];
#pragma unroll
        for (int off = 4; off > 0; off >>= 1) mm = fmaxf(mm, __shfl_xor_sync(0xffu, mm, off));
        red[tid] = mm;
    }
    __syncthreads();
    const float gm = red[0];
    float e = expf(v - gm);
    float ssum = e;
#pragma unroll
    for (int off = 16; off > 0; off >>= 1) ssum += __shfl_xor_sync(0xffffffffu, ssum, off);
    __syncthreads();
    if (ln == 0) red[wp] = ssum;
    __syncthreads();
    if (tid < 8) {
        float s2 = red[tid];
#pragma unroll
        for (int off = 4; off > 0; off >>= 1) s2 += __shfl_xor_sync(0xffu, s2, off);
        red[tid] = s2;
    }
    __syncthreads();
    const float tot = red[0];
    sc[tid] = e / tot;
    __syncthreads();
    float a0 = 0.0f, a1 = 0.0f;
    for (int s = 0; s < 256; s++) {
        const float a = sc[s];
        a0 += a * g_sentout[s][tid];
        a1 += a * g_sentout[s][tid + 256];
    }
    docv[tid] = a0; docv[tid + 256] = a1;
    __syncthreads();
    for (int o = wp; o < 10; o += 8) {
        const float* wr = &clsW[o * 512];
        float d = 0.0f;
#pragma unroll
        for (int i = 0; i < 4; i++) {
            float4 x = *(const float4*)&docv[ln * 16 + i * 4];
            float4 w = *(const float4*)&wr[ln * 16 + i * 4];
            d += x.x * w.x + x.y * w.y + x.z * w.z + x.w * w.w;
        }
#pragma unroll
        for (int off = 16; off > 0; off >>= 1) d += __shfl_xor_sync(0xffffffffu, d, off);
        if (ln == 0) lg[o] = d + clsB[o];
    }
    __syncthreads();
    if (tid == 0) {
        float mm = lg[0];
        for (int i = 1; i < 10; i++) mm = fmaxf(mm, lg[i]);
        float s2 = 0.0f;
        float ee[10];
        for (int i = 0; i < 10; i++) { ee[i] = expf(lg[i] - mm); s2 += ee[i]; }
        for (int i = 0; i < 10; i++) out[i] = ee[i] / s2;
    }
}

// ---------------- launch ----------------
extern "C" void kernel_launch(void* const* d_in, const int* in_sizes, int n_in,
                              void* d_out, int out_size) {
    const int*   toks  = (const int*)d_in[0];
    const float* emb   = (const float*)d_in[1];
    const float* wWihF = (const float*)d_in[2];
    const float* wWhhF = (const float*)d_in[3];
    const float* wBihF = (const float*)d_in[4];
    const float* wBhhF = (const float*)d_in[5];
    const float* wWihB = (const float*)d_in[6];
    const float* wWhhB = (const float*)d_in[7];
    const float* wBihB = (const float*)d_in[8];
    const float* wBhhB = (const float*)d_in[9];
    const float* sWihF = (const float*)d_in[10];
    const float* sWhhF = (const float*)d_in[11];
    const float* sBihF = (const float*)d_in[12];
    const float* sBhhF = (const float*)d_in[13];
    const float* sWihB = (const float*)d_in[14];
    const float* sWhhB = (const float*)d_in[15];
    const float* sBihB = (const float*)d_in[16];
    const float* sBhhB = (const float*)d_in[17];
    const float* wAttW = (const float*)d_in[18];
    const float* wAttB = (const float*)d_in[19];
    const float* sAttW = (const float*)d_in[20];
    const float* sAttB = (const float*)d_in[21];
    const float* clsW  = (const float*)d_in[22];
    const float* clsB  = (const float*)d_in[23];
    float* out = (float*)d_out;

    const int WREC_SMEM = (2 * 32 * 388 + 32 * 256 + 2 * 128 * 25 + 96) * 4;  // 158080
    cudaFuncSetAttribute(k_word_rec, cudaFuncAttributeMaxDynamicSharedMemorySize, WREC_SMEM);

    k_zero_bars<<<1, 32>>>();
    k_zero_bars<<<1, 32>>>();   // dummies: put k_word_gates in the ncu-captured slot (idx 3)
    k_zero_bars<<<1, 32>>>();
    dim3 g1(24, 256);
    k_word_gates<<<g1, 256>>>(toks, emb, wWihF, wWihB, wBihF, wBihB);
    k_word_rec<<<128, 256, WREC_SMEM>>>(wWhhF, wWhhB, wBhhF, wBhhB);
    k_word_attn<<<256, 256>>>(wAttW, wAttB);
    dim3 g2(24, 4);
    k_sent_gates<<<g2, 256>>>(sWihF, sWihB, sBihF, sBihB);
    k_sent_rec<<<16, 384>>>(sWhhF, sWhhB, sBhhF, sBhhB);
    k_doc<<<1, 256>>>(sAttW, sAttB, clsW, clsB, out);
}